// round 1
// baseline (speedup 1.0000x reference)
#include <cuda_runtime.h>

#define TOK 131072   // B*H*W = 32*64*64 tokens
#define CD  256

// ---------------- scratch (device globals; no allocations allowed) ----------
__device__ float g_Q[TOK * CD];
__device__ float g_K[TOK * CD];
__device__ float g_V[TOK * CD];
__device__ float g_O[TOK * CD];
__device__ float g_bias[225 * 8];

// ---------------- f32x2 packed-FMA helpers (Blackwell dual-pump fp32) -------
__device__ __forceinline__ unsigned long long pack2(float x, float y) {
    unsigned long long v;
    asm("mov.b64 %0, {%1,%2};" : "=l"(v) : "f"(x), "f"(y));
    return v;
}
__device__ __forceinline__ float2 unpack2(unsigned long long v) {
    float2 r;
    asm("mov.b64 {%0,%1}, %2;" : "=f"(r.x), "=f"(r.y) : "l"(v));
    return r;
}
__device__ __forceinline__ void fma2(unsigned long long& d, unsigned long long a,
                                     unsigned long long b) {
    asm("fma.rn.f32x2 %0, %1, %2, %0;" : "+l"(d) : "l"(a), "l"(b));
}

// token index (window order) -> row in the [B,H,W] image (shift+partition map)
__device__ __forceinline__ int rowmap(int m) {
    int win = m >> 6, n = m & 63;
    int b = win >> 6, w = win & 63;
    int wy = w >> 3, wx = w & 7;
    int iy = n >> 3, ix = n & 7;
    int gi = (wy * 8 + iy + 4) & 63;
    int gj = (wx * 8 + ix + 4) & 63;
    return (b * 64 + gi) * 64 + gj;
}

// ---------------- CPB-MLP: continuous relative position bias table ----------
__device__ __forceinline__ float cpb_coord(int a) {
    float r = (float)(a - 7);
    float v = r * (8.0f / 7.0f);
    float s = (v > 0.f) ? 1.f : ((v < 0.f) ? -1.f : 0.f);
    return s * log2f(fabsf(v) + 1.f) * (1.0f / 3.0f);  // log2(8)=3
}

__global__ void cpb_kernel(const float* __restrict__ w1, const float* __restrict__ b1,
                           const float* __restrict__ w2) {
    int t = threadIdx.x;
    if (t >= 225) return;
    float ta = cpb_coord(t / 15);
    float tb = cpb_coord(t % 15);
    float acc[8];
#pragma unroll
    for (int h = 0; h < 8; h++) acc[h] = 0.f;
    for (int j = 0; j < 512; j++) {
        float hd = ta * w1[2 * j] + tb * w1[2 * j + 1] + b1[j];
        hd = fmaxf(hd, 0.f);
#pragma unroll
        for (int h = 0; h < 8; h++) acc[h] += hd * w2[h * 512 + j];
    }
#pragma unroll
    for (int h = 0; h < 8; h++) g_bias[t * 8 + h] = 16.f / (1.f + expf(-acc[h]));
}

// ---------------- fp32 GEMM: C[M,256] = A[M,256] @ W[256,256]^T + bias ------
// 128x128 block tile, TK=16, 8x8 microtile (split fragments), f32x2 FMAs.
// GATHER: A rows permuted through rowmap (shift+window partition of x)
// SCATTER: C rows permuted through rowmap (window reverse + un-shift)
template <bool GATHER, bool SCATTER>
__global__ void __launch_bounds__(256) gemm_kernel(const float* __restrict__ A,
                                                   const float* __restrict__ W,
                                                   const float* __restrict__ bias,
                                                   float* __restrict__ C) {
    __shared__ __align__(16) float As[16][132];
    __shared__ __align__(16) float Bs[16][132];

    const int t = threadIdx.x;
    const int m0 = blockIdx.y * 128;
    const int n0 = blockIdx.x * 128;

    // ---- loader mapping: each thread stages 2 float4 of A and 2 of B per k-tile
    const int lr = t >> 2;        // 0..63
    const int lq = t & 3;         // quad within 16-wide k slice
    int ra0 = m0 + lr, ra1 = m0 + 64 + lr;
    if (GATHER) { ra0 = rowmap(ra0); ra1 = rowmap(ra1); }
    const float* pa0 = A + (size_t)ra0 * 256 + lq * 4;
    const float* pa1 = A + (size_t)ra1 * 256 + lq * 4;
    const float* pb0 = W + (size_t)(n0 + lr) * 256 + lq * 4;
    const float* pb1 = W + (size_t)(n0 + 64 + lr) * 256 + lq * 4;

    // ---- compute mapping: 16x16 threads, each owns rows {4r..,64+4r..}, cols {4c..,64+4c..}
    const int r = t >> 4;
    const int c = t & 15;

    unsigned long long acc[8][4];
#pragma unroll
    for (int i = 0; i < 8; i++)
#pragma unroll
        for (int p = 0; p < 4; p++) acc[i][p] = 0ull;

    float4 sa0 = *(const float4*)pa0;
    float4 sa1 = *(const float4*)pa1;
    float4 sb0 = *(const float4*)pb0;
    float4 sb1 = *(const float4*)pb1;

    for (int kt = 0; kt < 16; kt++) {
        __syncthreads();
#pragma unroll
        for (int u = 0; u < 4; u++) {
            As[lq * 4 + u][lr]      = ((float*)&sa0)[u];
            As[lq * 4 + u][64 + lr] = ((float*)&sa1)[u];
            Bs[lq * 4 + u][lr]      = ((float*)&sb0)[u];
            Bs[lq * 4 + u][64 + lr] = ((float*)&sb1)[u];
        }
        __syncthreads();
        if (kt < 15) {  // prefetch next k-tile into registers (hide global latency)
            int off = (kt + 1) * 16;
            sa0 = *(const float4*)(pa0 + off);
            sa1 = *(const float4*)(pa1 + off);
            sb0 = *(const float4*)(pb0 + off);
            sb1 = *(const float4*)(pb1 + off);
        }
#pragma unroll
        for (int k = 0; k < 16; k++) {
            float4 a0 = *(const float4*)&As[k][4 * r];
            float4 a1 = *(const float4*)&As[k][64 + 4 * r];
            ulonglong2 b0 = *(const ulonglong2*)&Bs[k][4 * c];
            ulonglong2 b1 = *(const ulonglong2*)&Bs[k][64 + 4 * c];
            float av[8] = {a0.x, a0.y, a0.z, a0.w, a1.x, a1.y, a1.z, a1.w};
#pragma unroll
            for (int i = 0; i < 8; i++) {
                unsigned long long ap = pack2(av[i], av[i]);
                fma2(acc[i][0], ap, b0.x);
                fma2(acc[i][1], ap, b0.y);
                fma2(acc[i][2], ap, b1.x);
                fma2(acc[i][3], ap, b1.y);
            }
        }
    }

    // ---- epilogue: add bias, optional scatter of rows
    const int c0 = n0 + 4 * c;
    const int c1 = n0 + 64 + 4 * c;
    float bb0x = bias[c0],     bb0y = bias[c0 + 1], bb0z = bias[c0 + 2], bb0w = bias[c0 + 3];
    float bb1x = bias[c1],     bb1y = bias[c1 + 1], bb1z = bias[c1 + 2], bb1w = bias[c1 + 3];
#pragma unroll
    for (int i = 0; i < 8; i++) {
        int gm = m0 + ((i < 4) ? (4 * r + i) : (64 + 4 * r + (i - 4)));
        int grow = SCATTER ? rowmap(gm) : gm;
        float* pc = C + (size_t)grow * 256;
        float2 p0 = unpack2(acc[i][0]);
        float2 p1 = unpack2(acc[i][1]);
        float2 p2 = unpack2(acc[i][2]);
        float2 p3 = unpack2(acc[i][3]);
        float4 o0 = make_float4(p0.x + bb0x, p0.y + bb0y, p1.x + bb0z, p1.y + bb0w);
        float4 o1 = make_float4(p2.x + bb1x, p2.y + bb1y, p3.x + bb1z, p3.y + bb1w);
        *(float4*)&pc[c0] = o0;
        *(float4*)&pc[c1] = o1;
    }
}

// ---------------- attention: one block per (window, head) -------------------
__global__ void __launch_bounds__(256) attn_kernel(const float* __restrict__ ls) {
    __shared__ __align__(16) float QsT[32][68];   // k-major (transposed)
    __shared__ __align__(16) float KsT[32][68];
    __shared__ __align__(16) float Vs[64][36];    // row-major
    __shared__ __align__(16) float Ps[64][65];
    __shared__ float biasH[225];
    __shared__ int cntS[64];

    const int t = threadIdx.x;
    const int h = blockIdx.x;
    const int win = blockIdx.y;
    const size_t base = ((size_t)win * 64) * 256 + h * 32;

    if (t < 225) biasH[t] = g_bias[t * 8 + h];
    {
        int w = win & 63;
        int wy = w >> 3, wx = w & 7;
        if (t < 64) {
            int iy = t >> 3, ix = t & 7;
            int si = wy * 8 + iy, sj = wx * 8 + ix;
            int rh = (si < 56) ? 0 : ((si < 60) ? 1 : 2);
            int rw = (sj < 56) ? 0 : ((sj < 60) ? 1 : 2);
            cntS[t] = rh * 3 + rw;
        }
    }

    // load Q,K transposed + V row-major
#pragma unroll
    for (int ff = 0; ff < 2; ff++) {
        int f = t + ff * 256;
        int row = f >> 3, qd = f & 7;
        size_t ga = base + (size_t)row * 256 + qd * 4;
        float4 qv = *(const float4*)&g_Q[ga];
        float4 kv = *(const float4*)&g_K[ga];
        float4 vv = *(const float4*)&g_V[ga];
#pragma unroll
        for (int u = 0; u < 4; u++) {
            QsT[qd * 4 + u][row] = ((float*)&qv)[u];
            KsT[qd * 4 + u][row] = ((float*)&kv)[u];
        }
        *(float4*)&Vs[row][qd * 4] = vv;
    }
    __syncthreads();

    // cosine normalization of q,k rows
    if (t < 128) {
        int rI = t & 63;
        float(*Mt)[68] = (t < 64) ? QsT : KsT;
        float s = 0.f;
#pragma unroll
        for (int kk = 0; kk < 32; kk++) {
            float v = Mt[kk][rI];
            s += v * v;
        }
        float inv = 1.f / fmaxf(sqrtf(s), 1e-12f);
#pragma unroll
        for (int kk = 0; kk < 32; kk++) Mt[kk][rI] *= inv;
    }
    __syncthreads();

    const float scale = __expf(fminf(ls[h], 4.6051702f));  // exp(min(ls, ln 100))

    // S = qn @ kn^T : 4x4 microtile per thread
    const int rn = t >> 4;
    const int cn = t & 15;
    unsigned long long sp[4][2];
#pragma unroll
    for (int i = 0; i < 4; i++) { sp[i][0] = 0ull; sp[i][1] = 0ull; }
#pragma unroll
    for (int kk = 0; kk < 32; kk++) {
        float4 a = *(const float4*)&QsT[kk][4 * rn];
        ulonglong2 b = *(const ulonglong2*)&KsT[kk][4 * cn];
#pragma unroll
        for (int i = 0; i < 4; i++) {
            unsigned long long ap = pack2(((float*)&a)[i], ((float*)&a)[i]);
            fma2(sp[i][0], ap, b.x);
            fma2(sp[i][1], ap, b.y);
        }
    }

    // scale + bias + shift-mask, then softmax (shfl over the 16-lane row group)
    float sv[4][4];
#pragma unroll
    for (int i = 0; i < 4; i++) {
        float2 e0 = unpack2(sp[i][0]);
        float2 e1 = unpack2(sp[i][1]);
        sv[i][0] = e0.x; sv[i][1] = e0.y; sv[i][2] = e1.x; sv[i][3] = e1.y;
    }
#pragma unroll
    for (int i = 0; i < 4; i++) {
        int n = 4 * rn + i;
        int iy = n >> 3, ix = n & 7;
        int cc = cntS[n];
#pragma unroll
        for (int j = 0; j < 4; j++) {
            int m = 4 * cn + j;
            int jy = m >> 3, jx = m & 7;
            float msk = (cc != cntS[m]) ? -100.f : 0.f;
            sv[i][j] = sv[i][j] * scale + biasH[(iy - jy + 7) * 15 + (ix - jx + 7)] + msk;
        }
    }
#pragma unroll
    for (int i = 0; i < 4; i++) {
        float mx = fmaxf(fmaxf(sv[i][0], sv[i][1]), fmaxf(sv[i][2], sv[i][3]));
        mx = fmaxf(mx, __shfl_xor_sync(0xffffffffu, mx, 1));
        mx = fmaxf(mx, __shfl_xor_sync(0xffffffffu, mx, 2));
        mx = fmaxf(mx, __shfl_xor_sync(0xffffffffu, mx, 4));
        mx = fmaxf(mx, __shfl_xor_sync(0xffffffffu, mx, 8));
        float se = 0.f;
#pragma unroll
        for (int j = 0; j < 4; j++) {
            sv[i][j] = __expf(sv[i][j] - mx);
            se += sv[i][j];
        }
        se += __shfl_xor_sync(0xffffffffu, se, 1);
        se += __shfl_xor_sync(0xffffffffu, se, 2);
        se += __shfl_xor_sync(0xffffffffu, se, 4);
        se += __shfl_xor_sync(0xffffffffu, se, 8);
        float inv = 1.f / se;
        int n = 4 * rn + i;
#pragma unroll
        for (int j = 0; j < 4; j++) Ps[n][4 * cn + j] = sv[i][j] * inv;
    }
    __syncthreads();

    // O = P @ V : each thread owns (row n, 8 of 32 head dims)
    const int n = t >> 2;
    const int q = t & 3;
    unsigned long long ov[4] = {0ull, 0ull, 0ull, 0ull};
#pragma unroll 8
    for (int m = 0; m < 64; m++) {
        float p = Ps[n][m];
        unsigned long long pp = pack2(p, p);
        ulonglong2 v0 = *(const ulonglong2*)&Vs[m][q * 8];
        ulonglong2 v1 = *(const ulonglong2*)&Vs[m][q * 8 + 4];
        fma2(ov[0], pp, v0.x);
        fma2(ov[1], pp, v0.y);
        fma2(ov[2], pp, v1.x);
        fma2(ov[3], pp, v1.y);
    }
    float* po = &g_O[base + (size_t)n * 256 + q * 8];
    *(ulonglong2*)po = make_ulonglong2(ov[0], ov[1]);
    *(ulonglong2*)(po + 4) = make_ulonglong2(ov[2], ov[3]);
}

// ---------------- launch ----------------------------------------------------
extern "C" void kernel_launch(void* const* d_in, const int* in_sizes, int n_in,
                              void* d_out, int out_size) {
    const float* x  = (const float*)d_in[0];
    const float* Wq = (const float*)d_in[1];
    const float* bq = (const float*)d_in[2];
    const float* Wk = (const float*)d_in[3];
    const float* bk = (const float*)d_in[4];
    const float* Wv = (const float*)d_in[5];
    const float* bv = (const float*)d_in[6];
    const float* Wo = (const float*)d_in[7];
    const float* bo = (const float*)d_in[8];
    const float* ls = (const float*)d_in[9];
    const float* w1 = (const float*)d_in[10];
    const float* b1 = (const float*)d_in[11];
    const float* w2 = (const float*)d_in[12];
    float* out = (float*)d_out;

    float *pQ, *pK, *pV, *pO;
    cudaGetSymbolAddress((void**)&pQ, g_Q);
    cudaGetSymbolAddress((void**)&pK, g_K);
    cudaGetSymbolAddress((void**)&pV, g_V);
    cudaGetSymbolAddress((void**)&pO, g_O);

    cpb_kernel<<<1, 256>>>(w1, b1, w2);

    dim3 gg(2, 1024);
    gemm_kernel<true, false><<<gg, 256>>>(x, Wq, bq, pQ);
    gemm_kernel<true, false><<<gg, 256>>>(x, Wk, bk, pK);
    gemm_kernel<true, false><<<gg, 256>>>(x, Wv, bv, pV);

    attn_kernel<<<dim3(8, 2048), 256>>>(ls);

    gemm_kernel<false, true><<<gg, 256>>>(pO, Wo, bo, out);
}

// round 4
// speedup vs baseline: 1.2910x; 1.2910x over previous
#include <cuda_runtime.h>
#include <cuda_bf16.h>
#include <cstdint>

#define TOK 131072   // B*H*W = 32*64*64 tokens
#define CD  256

// ---------------- scratch (device globals; no allocations allowed) ----------
__device__ float g_Q[TOK * CD];
__device__ float g_K[TOK * CD];
__device__ float g_V[TOK * CD];
__device__ float g_O[TOK * CD];
__device__ float g_bias[225 * 8];

// ---------------- f32x2 packed-FMA helpers (attention) ----------------------
__device__ __forceinline__ unsigned long long pack2(float x, float y) {
    unsigned long long v;
    asm("mov.b64 %0, {%1,%2};" : "=l"(v) : "f"(x), "f"(y));
    return v;
}
__device__ __forceinline__ float2 unpack2(unsigned long long v) {
    float2 r;
    asm("mov.b64 {%0,%1}, %2;" : "=f"(r.x), "=f"(r.y) : "l"(v));
    return r;
}
__device__ __forceinline__ void fma2(unsigned long long& d, unsigned long long a,
                                     unsigned long long b) {
    asm("fma.rn.f32x2 %0, %1, %2, %0;" : "+l"(d) : "l"(a), "l"(b));
}

// token index (window order) -> row in the [B,H,W] image (shift+partition map)
__device__ __forceinline__ int rowmap(int m) {
    int win = m >> 6, n = m & 63;
    int b = win >> 6, w = win & 63;
    int wy = w >> 3, wx = w & 7;
    int iy = n >> 3, ix = n & 7;
    int gi = (wy * 8 + iy + 4) & 63;
    int gj = (wx * 8 + ix + 4) & 63;
    return (b * 64 + gi) * 64 + gj;
}

// ---------------- bf16 split helpers ----------------------------------------
__device__ __forceinline__ uint32_t cvt_hi2(float a, float b, float& ra, float& rb) {
    __nv_bfloat16 ha = __float2bfloat16_rn(a), hb = __float2bfloat16_rn(b);
    ra = a - __bfloat162float(ha);
    rb = b - __bfloat162float(hb);
    __nv_bfloat162 p = __halves2bfloat162(ha, hb);
    return *(uint32_t*)&p;
}
__device__ __forceinline__ uint32_t cvt2(float a, float b) {
    __nv_bfloat162 p = __halves2bfloat162(__float2bfloat16_rn(a), __float2bfloat16_rn(b));
    return *(uint32_t*)&p;
}

__device__ __forceinline__ void mma_bf16(float* d, const uint32_t* a, const uint32_t* b) {
    asm volatile(
        "mma.sync.aligned.m16n8k16.row.col.f32.bf16.bf16.f32 "
        "{%0,%1,%2,%3}, {%4,%5,%6,%7}, {%8,%9}, {%0,%1,%2,%3};"
        : "+f"(d[0]), "+f"(d[1]), "+f"(d[2]), "+f"(d[3])
        : "r"(a[0]), "r"(a[1]), "r"(a[2]), "r"(a[3]), "r"(b[0]), "r"(b[1]));
}

// ---------------- CPB-MLP ----------------------------------------------------
__device__ __forceinline__ float cpb_coord(int a) {
    float r = (float)(a - 7);
    float v = r * (8.0f / 7.0f);
    float s = (v > 0.f) ? 1.f : ((v < 0.f) ? -1.f : 0.f);
    return s * log2f(fabsf(v) + 1.f) * (1.0f / 3.0f);
}

__global__ void cpb_kernel(const float* __restrict__ w1, const float* __restrict__ b1,
                           const float* __restrict__ w2) {
    int t = threadIdx.x;
    if (t >= 225) return;
    float ta = cpb_coord(t / 15);
    float tb = cpb_coord(t % 15);
    float acc[8];
#pragma unroll
    for (int h = 0; h < 8; h++) acc[h] = 0.f;
    for (int j = 0; j < 512; j++) {
        float hd = ta * w1[2 * j] + tb * w1[2 * j + 1] + b1[j];
        hd = fmaxf(hd, 0.f);
#pragma unroll
        for (int h = 0; h < 8; h++) acc[h] += hd * w2[h * 512 + j];
    }
#pragma unroll
    for (int h = 0; h < 8; h++) g_bias[t * 8 + h] = 16.f / (1.f + expf(-acc[h]));
}

// ---------------- split-bf16 mma.sync GEMM ----------------------------------
// C[M,256] = A[M,256] @ W[256,256]^T + bias, with A = Ahi + Alo (bf16 split).
// CTA tile 128x128, 8 warps as 2(m)x4(n) of 64x32 warp tiles, K chunks of 32,
// double-buffered smem with in-loader fp32->bf16 hi/lo conversion.
// GATHER: A rows via rowmap;  SCATTER: C rows via rowmap.

#define LDAB 36                       // bf16 elems per smem row (72B, 8B aligned)
#define MAT_BYTES (128 * LDAB * 2)    // 9216
#define AH_OFF 0
#define AL_OFF MAT_BYTES
#define BH_OFF (2 * MAT_BYTES)
#define BL_OFF (3 * MAT_BYTES)
#define STAGE_BYTES (4 * MAT_BYTES)   // 36864
#define GEMM_SMEM (2 * STAGE_BYTES)   // 73728

template <bool GATHER, bool SCATTER>
__global__ void __launch_bounds__(256) gemm_mma(const float* __restrict__ A,
                                                const float* __restrict__ W,
                                                const float* __restrict__ bias,
                                                float* __restrict__ C) {
    extern __shared__ char sm[];
    const int t = threadIdx.x;
    const int n0 = blockIdx.x * 128;
    const int m0 = blockIdx.y * 128;

    // ---- loader mapping: 4 float4 of A and 4 of B per 32-wide k chunk ----
    const float* aptr[4];
    const float* bptr[4];
    int sIdx[4];  // uint2 index into a 128xLDAB bf16 matrix
#pragma unroll
    for (int i = 0; i < 4; i++) {
        int idx = t + i * 256;
        int r = idx >> 3, c4 = idx & 7;
        int gr = m0 + r;
        if (GATHER) gr = rowmap(gr);
        aptr[i] = A + (size_t)gr * 256 + c4 * 4;
        bptr[i] = W + (size_t)(n0 + r) * 256 + c4 * 4;
        sIdx[i] = r * 9 + c4;
    }

    // ---- warp/lane fragment mapping ----
    const int w = t >> 5, lane = t & 31;
    const int wm = w >> 2, wn = w & 3;            // warp grid 2(m) x 4(n)
    const int g = lane >> 2, tg = lane & 3;
    const int abase0 = (wm * 64 + g) * 18 + tg;   // 18 = LDAB/2 32-bit words/row
    const int bbase0 = (wn * 32 + g) * 18 + tg;

    float acc[4][4][4];
#pragma unroll
    for (int i = 0; i < 4; i++)
#pragma unroll
        for (int j = 0; j < 4; j++)
#pragma unroll
            for (int p = 0; p < 4; p++) acc[i][j][p] = 0.f;

    float4 av[4], bv[4];

    // convert + store one chunk's regs into stage buffer
    auto store_stage = [&](int buf) {
        char* st = sm + buf * STAGE_BYTES;
        uint2* ah = (uint2*)(st + AH_OFF);
        uint2* al = (uint2*)(st + AL_OFF);
        uint2* bh = (uint2*)(st + BH_OFF);
        uint2* bl = (uint2*)(st + BL_OFF);
#pragma unroll
        for (int i = 0; i < 4; i++) {
            float rx, ry, rz, rw;
            uint32_t h0 = cvt_hi2(av[i].x, av[i].y, rx, ry);
            uint32_t h1 = cvt_hi2(av[i].z, av[i].w, rz, rw);
            ah[sIdx[i]] = make_uint2(h0, h1);
            al[sIdx[i]] = make_uint2(cvt2(rx, ry), cvt2(rz, rw));
            uint32_t g0 = cvt_hi2(bv[i].x, bv[i].y, rx, ry);
            uint32_t g1 = cvt_hi2(bv[i].z, bv[i].w, rz, rw);
            bh[sIdx[i]] = make_uint2(g0, g1);
            bl[sIdx[i]] = make_uint2(cvt2(rx, ry), cvt2(rz, rw));
        }
    };

    // ---- prologue: chunk0 -> stage0; chunk1 -> regs ----
#pragma unroll
    for (int i = 0; i < 4; i++) { av[i] = *(const float4*)aptr[i]; bv[i] = *(const float4*)bptr[i]; }
    store_stage(0);
#pragma unroll
    for (int i = 0; i < 4; i++) { av[i] = *(const float4*)(aptr[i] + 32); bv[i] = *(const float4*)(bptr[i] + 32); }

    for (int c = 0; c < 8; c++) {
        const int buf = c & 1;
        if (c + 1 < 8) store_stage(buf ^ 1);      // chunk c+1 regs -> opposite buffer
        if (c + 2 < 8) {
            const int off = (c + 2) * 32;
#pragma unroll
            for (int i = 0; i < 4; i++) {
                av[i] = *(const float4*)(aptr[i] + off);
                bv[i] = *(const float4*)(bptr[i] + off);
            }
        }
        __syncthreads();                          // stage stores visible

        const char* st = sm + buf * STAGE_BYTES;
        const uint32_t* Ah = (const uint32_t*)(st + AH_OFF);
        const uint32_t* Al = (const uint32_t*)(st + AL_OFF);
        const uint32_t* Bh = (const uint32_t*)(st + BH_OFF);
        const uint32_t* Bl = (const uint32_t*)(st + BL_OFF);

#pragma unroll
        for (int half = 0; half < 2; half++) {
            const int ws = half * 8;
            uint32_t ahf[4][4], alf[4][4], bhf[4][2], blf[4][2];
#pragma unroll
            for (int i = 0; i < 4; i++) {
                int ba = abase0 + i * 288 + ws;   // 288 = 16 rows * 18 words
                ahf[i][0] = Ah[ba];       ahf[i][1] = Ah[ba + 144];
                ahf[i][2] = Ah[ba + 4];   ahf[i][3] = Ah[ba + 148];
                alf[i][0] = Al[ba];       alf[i][1] = Al[ba + 144];
                alf[i][2] = Al[ba + 4];   alf[i][3] = Al[ba + 148];
            }
#pragma unroll
            for (int j = 0; j < 4; j++) {
                int bb = bbase0 + j * 144 + ws;   // 144 = 8 rows * 18 words
                bhf[j][0] = Bh[bb];  bhf[j][1] = Bh[bb + 4];
                blf[j][0] = Bl[bb];  blf[j][1] = Bl[bb + 4];
            }
#pragma unroll
            for (int i = 0; i < 4; i++)
#pragma unroll
                for (int j = 0; j < 4; j++) {
                    mma_bf16(acc[i][j], ahf[i], bhf[j]);
                    mma_bf16(acc[i][j], ahf[i], blf[j]);
                    mma_bf16(acc[i][j], alf[i], bhf[j]);
                }
        }
        __syncthreads();                          // reads done before buf reuse
    }

    // ---- epilogue: bias add + (optional scatter) store, float2 per frag row --
#pragma unroll
    for (int i = 0; i < 4; i++) {
        int row0 = m0 + wm * 64 + i * 16 + g;
        int row1 = row0 + 8;
        int gm0 = SCATTER ? rowmap(row0) : row0;
        int gm1 = SCATTER ? rowmap(row1) : row1;
        float* p0 = C + (size_t)gm0 * 256;
        float* p1 = C + (size_t)gm1 * 256;
#pragma unroll
        for (int j = 0; j < 4; j++) {
            int col = n0 + wn * 32 + j * 8 + 2 * tg;
            float2 bb = *(const float2*)&bias[col];
            *(float2*)&p0[col] = make_float2(acc[i][j][0] + bb.x, acc[i][j][1] + bb.y);
            *(float2*)&p1[col] = make_float2(acc[i][j][2] + bb.x, acc[i][j][3] + bb.y);
        }
    }
}

// ---------------- attention: one block per (window, head) -------------------
__global__ void __launch_bounds__(256) attn_kernel(const float* __restrict__ ls) {
    __shared__ __align__(16) float QsT[32][68];   // k-major (transposed)
    __shared__ __align__(16) float KsT[32][68];
    __shared__ __align__(16) float Vs[64][36];    // row-major
    __shared__ __align__(16) float Ps[64][65];
    __shared__ float biasH[225];
    __shared__ int cntS[64];

    const int t = threadIdx.x;
    const int h = blockIdx.x;
    const int win = blockIdx.y;
    const size_t base = ((size_t)win * 64) * 256 + h * 32;

    if (t < 225) biasH[t] = g_bias[t * 8 + h];
    {
        int w = win & 63;
        int wy = w >> 3, wx = w & 7;
        if (t < 64) {
            int iy = t >> 3, ix = t & 7;
            int si = wy * 8 + iy, sj = wx * 8 + ix;
            int rh = (si < 56) ? 0 : ((si < 60) ? 1 : 2);
            int rw = (sj < 56) ? 0 : ((sj < 60) ? 1 : 2);
            cntS[t] = rh * 3 + rw;
        }
    }

    // load Q,K transposed + V row-major
#pragma unroll
    for (int ff = 0; ff < 2; ff++) {
        int f = t + ff * 256;
        int row = f >> 3, qd = f & 7;
        size_t ga = base + (size_t)row * 256 + qd * 4;
        float4 qv = *(const float4*)&g_Q[ga];
        float4 kv = *(const float4*)&g_K[ga];
        float4 vv = *(const float4*)&g_V[ga];
#pragma unroll
        for (int u = 0; u < 4; u++) {
            QsT[qd * 4 + u][row] = ((float*)&qv)[u];
            KsT[qd * 4 + u][row] = ((float*)&kv)[u];
        }
        *(float4*)&Vs[row][qd * 4] = vv;
    }
    __syncthreads();

    // cosine normalization of q,k rows
    if (t < 128) {
        int rI = t & 63;
        float(*Mt)[68] = (t < 64) ? QsT : KsT;
        float s = 0.f;
#pragma unroll
        for (int kk = 0; kk < 32; kk++) {
            float v = Mt[kk][rI];
            s += v * v;
        }
        float inv = 1.f / fmaxf(sqrtf(s), 1e-12f);
#pragma unroll
        for (int kk = 0; kk < 32; kk++) Mt[kk][rI] *= inv;
    }
    __syncthreads();

    const float scale = __expf(fminf(ls[h], 4.6051702f));  // exp(min(ls, ln 100))

    // S = qn @ kn^T : 4x4 microtile per thread
    const int rn = t >> 4;
    const int cn = t & 15;
    unsigned long long sp[4][2];
#pragma unroll
    for (int i = 0; i < 4; i++) { sp[i][0] = 0ull; sp[i][1] = 0ull; }
#pragma unroll
    for (int kk = 0; kk < 32; kk++) {
        float4 a = *(const float4*)&QsT[kk][4 * rn];
        ulonglong2 b = *(const ulonglong2*)&KsT[kk][4 * cn];
#pragma unroll
        for (int i = 0; i < 4; i++) {
            unsigned long long ap = pack2(((float*)&a)[i], ((float*)&a)[i]);
            fma2(sp[i][0], ap, b.x);
            fma2(sp[i][1], ap, b.y);
        }
    }

    // scale + bias + shift-mask, then softmax (shfl over the 16-lane row group)
    float sv[4][4];
#pragma unroll
    for (int i = 0; i < 4; i++) {
        float2 e0 = unpack2(sp[i][0]);
        float2 e1 = unpack2(sp[i][1]);
        sv[i][0] = e0.x; sv[i][1] = e0.y; sv[i][2] = e1.x; sv[i][3] = e1.y;
    }
#pragma unroll
    for (int i = 0; i < 4; i++) {
        int n = 4 * rn + i;
        int iy = n >> 3, ix = n & 7;
        int cc = cntS[n];
#pragma unroll
        for (int j = 0; j < 4; j++) {
            int m = 4 * cn + j;
            int jy = m >> 3, jx = m & 7;
            float msk = (cc != cntS[m]) ? -100.f : 0.f;
            sv[i][j] = sv[i][j] * scale + biasH[(iy - jy + 7) * 15 + (ix - jx + 7)] + msk;
        }
    }
#pragma unroll
    for (int i = 0; i < 4; i++) {
        float mx = fmaxf(fmaxf(sv[i][0], sv[i][1]), fmaxf(sv[i][2], sv[i][3]));
        mx = fmaxf(mx, __shfl_xor_sync(0xffffffffu, mx, 1));
        mx = fmaxf(mx, __shfl_xor_sync(0xffffffffu, mx, 2));
        mx = fmaxf(mx, __shfl_xor_sync(0xffffffffu, mx, 4));
        mx = fmaxf(mx, __shfl_xor_sync(0xffffffffu, mx, 8));
        float se = 0.f;
#pragma unroll
        for (int j = 0; j < 4; j++) {
            sv[i][j] = __expf(sv[i][j] - mx);
            se += sv[i][j];
        }
        se += __shfl_xor_sync(0xffffffffu, se, 1);
        se += __shfl_xor_sync(0xffffffffu, se, 2);
        se += __shfl_xor_sync(0xffffffffu, se, 4);
        se += __shfl_xor_sync(0xffffffffu, se, 8);
        float inv = 1.f / se;
        int n = 4 * rn + i;
#pragma unroll
        for (int j = 0; j < 4; j++) Ps[n][4 * cn + j] = sv[i][j] * inv;
    }
    __syncthreads();

    // O = P @ V : each thread owns (row n, 8 of 32 head dims)
    const int n = t >> 2;
    const int q = t & 3;
    unsigned long long ov[4] = {0ull, 0ull, 0ull, 0ull};
#pragma unroll 8
    for (int m = 0; m < 64; m++) {
        float p = Ps[n][m];
        unsigned long long pp = pack2(p, p);
        ulonglong2 v0 = *(const ulonglong2*)&Vs[m][q * 8];
        ulonglong2 v1 = *(const ulonglong2*)&Vs[m][q * 8 + 4];
        fma2(ov[0], pp, v0.x);
        fma2(ov[1], pp, v0.y);
        fma2(ov[2], pp, v1.x);
        fma2(ov[3], pp, v1.y);
    }
    float* po = &g_O[base + (size_t)n * 256 + q * 8];
    *(ulonglong2*)po = make_ulonglong2(ov[0], ov[1]);
    *(ulonglong2*)(po + 4) = make_ulonglong2(ov[2], ov[3]);
}

// ---------------- launch ----------------------------------------------------
extern "C" void kernel_launch(void* const* d_in, const int* in_sizes, int n_in,
                              void* d_out, int out_size) {
    const float* x  = (const float*)d_in[0];
    const float* Wq = (const float*)d_in[1];
    const float* bq = (const float*)d_in[2];
    const float* Wk = (const float*)d_in[3];
    const float* bk = (const float*)d_in[4];
    const float* Wv = (const float*)d_in[5];
    const float* bv = (const float*)d_in[6];
    const float* Wo = (const float*)d_in[7];
    const float* bo = (const float*)d_in[8];
    const float* ls = (const float*)d_in[9];
    const float* w1 = (const float*)d_in[10];
    const float* b1 = (const float*)d_in[11];
    const float* w2 = (const float*)d_in[12];
    float* out = (float*)d_out;

    float *pQ, *pK, *pV, *pO;
    cudaGetSymbolAddress((void**)&pQ, g_Q);
    cudaGetSymbolAddress((void**)&pK, g_K);
    cudaGetSymbolAddress((void**)&pV, g_V);
    cudaGetSymbolAddress((void**)&pO, g_O);

    cudaFuncSetAttribute(gemm_mma<true, false>,
                         cudaFuncAttributeMaxDynamicSharedMemorySize, GEMM_SMEM);
    cudaFuncSetAttribute(gemm_mma<false, true>,
                         cudaFuncAttributeMaxDynamicSharedMemorySize, GEMM_SMEM);

    cpb_kernel<<<1, 256>>>(w1, b1, w2);

    dim3 gg(2, 1024);
    gemm_mma<true, false><<<gg, 256, GEMM_SMEM>>>(x, Wq, bq, pQ);
    gemm_mma<true, false><<<gg, 256, GEMM_SMEM>>>(x, Wk, bk, pK);
    gemm_mma<true, false><<<gg, 256, GEMM_SMEM>>>(x, Wv, bv, pV);

    attn_kernel<<<dim3(8, 2048), 256>>>(ls);

    gemm_mma<false, true><<<gg, 256, GEMM_SMEM>>>(pO, Wo, bo, out);
}

// round 5
// speedup vs baseline: 1.4471x; 1.1209x over previous
#include <cuda_runtime.h>
#include <cuda_bf16.h>
#include <cstdint>

#define TOK 131072   // B*H*W = 32*64*64 tokens
#define CD  256

// ---------------- scratch (device globals; no allocations allowed) ----------
__device__ float g_Q[TOK * CD];
__device__ float g_K[TOK * CD];
__device__ float g_V[TOK * CD];
__device__ float g_O[TOK * CD];
__device__ float g_bias[225 * 8];
__device__ __nv_bfloat16 g_xh[TOK * CD], g_xl[TOK * CD];
__device__ __nv_bfloat16 g_oh[TOK * CD], g_ol[TOK * CD];
__device__ __nv_bfloat16 g_wh[4 * CD * CD], g_wl[4 * CD * CD];

// ---------------- helpers ----------------------------------------------------
__device__ __forceinline__ uint32_t smem_u32(const void* p) {
    uint32_t a;
    asm("{ .reg .u64 t; cvta.to.shared.u64 t, %1; cvt.u32.u64 %0, t; }"
        : "=r"(a) : "l"(p));
    return a;
}

__device__ __forceinline__ unsigned long long pack2(float x, float y) {
    unsigned long long v;
    asm("mov.b64 %0, {%1,%2};" : "=l"(v) : "f"(x), "f"(y));
    return v;
}
__device__ __forceinline__ float2 unpack2(unsigned long long v) {
    float2 r;
    asm("mov.b64 {%0,%1}, %2;" : "=f"(r.x), "=f"(r.y) : "l"(v));
    return r;
}
__device__ __forceinline__ void fma2(unsigned long long& d, unsigned long long a,
                                     unsigned long long b) {
    asm("fma.rn.f32x2 %0, %1, %2, %0;" : "+l"(d) : "l"(a), "l"(b));
}

// token index (window order) -> row in the [B,H,W] image (shift+partition map)
__device__ __forceinline__ int rowmap(int m) {
    int win = m >> 6, n = m & 63;
    int b = win >> 6, w = win & 63;
    int wy = w >> 3, wx = w & 7;
    int iy = n >> 3, ix = n & 7;
    int gi = (wy * 8 + iy + 4) & 63;
    int gj = (wx * 8 + ix + 4) & 63;
    return (b * 64 + gi) * 64 + gj;
}

__device__ __forceinline__ void mma_bf16(float* d, const uint32_t* a, const uint32_t* b) {
    asm volatile(
        "mma.sync.aligned.m16n8k16.row.col.f32.bf16.bf16.f32 "
        "{%0,%1,%2,%3}, {%4,%5,%6,%7}, {%8,%9}, {%0,%1,%2,%3};"
        : "+f"(d[0]), "+f"(d[1]), "+f"(d[2]), "+f"(d[3])
        : "r"(a[0]), "r"(a[1]), "r"(a[2]), "r"(a[3]), "r"(b[0]), "r"(b[1]));
}
__device__ __forceinline__ void ldm4(uint32_t* r, uint32_t addr) {
    asm volatile("ldmatrix.sync.aligned.m8n8.x4.shared.b16 {%0,%1,%2,%3}, [%4];"
                 : "=r"(r[0]), "=r"(r[1]), "=r"(r[2]), "=r"(r[3]) : "r"(addr));
}
#define CP16(s, g) asm volatile("cp.async.cg.shared.global [%0], [%1], 16;" :: "r"(s), "l"(g))
#define CPCOMMIT() asm volatile("cp.async.commit_group;" ::: "memory")
#define CPWAIT(n)  asm volatile("cp.async.wait_group %0;" :: "n"(n) : "memory")

// ---------------- fp32 -> bf16 hi/lo split pass ------------------------------
__global__ void split_kernel(const float* __restrict__ src, __nv_bfloat16* __restrict__ hi,
                             __nv_bfloat16* __restrict__ lo, int n4) {
    int i = blockIdx.x * blockDim.x + threadIdx.x;
    if (i >= n4) return;
    float4 v = ((const float4*)src)[i];
    __nv_bfloat16 h0 = __float2bfloat16_rn(v.x), h1 = __float2bfloat16_rn(v.y);
    __nv_bfloat16 h2 = __float2bfloat16_rn(v.z), h3 = __float2bfloat16_rn(v.w);
    __nv_bfloat16 l0 = __float2bfloat16_rn(v.x - __bfloat162float(h0));
    __nv_bfloat16 l1 = __float2bfloat16_rn(v.y - __bfloat162float(h1));
    __nv_bfloat16 l2 = __float2bfloat16_rn(v.z - __bfloat162float(h2));
    __nv_bfloat16 l3 = __float2bfloat16_rn(v.w - __bfloat162float(h3));
    ((__nv_bfloat162*)hi)[2 * i]     = __halves2bfloat162(h0, h1);
    ((__nv_bfloat162*)hi)[2 * i + 1] = __halves2bfloat162(h2, h3);
    ((__nv_bfloat162*)lo)[2 * i]     = __halves2bfloat162(l0, l1);
    ((__nv_bfloat162*)lo)[2 * i + 1] = __halves2bfloat162(l2, l3);
}

// ---------------- CPB-MLP (parallel over heads) ------------------------------
__device__ __forceinline__ float cpb_coord(int a) {
    float r = (float)(a - 7);
    float v = r * (8.0f / 7.0f);
    float s = (v > 0.f) ? 1.f : ((v < 0.f) ? -1.f : 0.f);
    return s * log2f(fabsf(v) + 1.f) * (1.0f / 3.0f);
}

__global__ void cpb_kernel(const float* __restrict__ w1, const float* __restrict__ b1,
                           const float* __restrict__ w2) {
    int t = threadIdx.x;
    int h = blockIdx.x;
    if (t >= 225) return;
    float ta = cpb_coord(t / 15);
    float tb = cpb_coord(t % 15);
    float acc = 0.f;
    for (int j = 0; j < 512; j++) {
        float hd = ta * w1[2 * j] + tb * w1[2 * j + 1] + b1[j];
        hd = fmaxf(hd, 0.f);
        acc += hd * w2[h * 512 + j];
    }
    g_bias[t * 8 + h] = 16.f / (1.f + expf(-acc));
}

// ---------------- split-bf16 mma GEMM, cp.async + ldmatrix -------------------
// C[M,256] = (Ah+Al)[M,256] @ (Bh+Bl)[256,256]^T + bias (3-term split product).
// CTA 128x128, 8 warps 2(m)x4(n) of 64x32 warp tiles; K chunks of 32,
// 2-stage cp.async pipeline; 80B-padded smem rows (conflict-free ldmatrix).
#define LDB    80                 // bytes per smem row (32 bf16 + 16B pad)
#define MATB   (128 * LDB)        // 10240
#define STAGEB (4 * MATB)         // 40960: Ah | Al | Bh | Bl
#define GSMEM  (2 * STAGEB)       // 81920

template <bool GATHER, bool SCATTER>
__global__ void __launch_bounds__(256, 2) gemm_mma2(
    const __nv_bfloat16* __restrict__ Ah_, const __nv_bfloat16* __restrict__ Al_,
    const __nv_bfloat16* __restrict__ Bh_, const __nv_bfloat16* __restrict__ Bl_,
    const float* __restrict__ bias, float* __restrict__ C) {
    extern __shared__ char sm[];
    const uint32_t sb = smem_u32(sm);
    const int t = threadIdx.x;
    const int n0 = blockIdx.x * 128, m0 = blockIdx.y * 128;

    // ---- loader: each thread owns (row rA, two 16B chunks) in all 4 matrices
    const int rA = t >> 1;
    const int cp0 = (t & 1) * 2;
    int garow = m0 + rA;
    if (GATHER) garow = rowmap(garow);
    const __nv_bfloat16* pAh = Ah_ + (size_t)garow * 256 + cp0 * 8;
    const __nv_bfloat16* pAl = Al_ + (size_t)garow * 256 + cp0 * 8;
    const __nv_bfloat16* pBh = Bh_ + (size_t)(n0 + rA) * 256 + cp0 * 8;
    const __nv_bfloat16* pBl = Bl_ + (size_t)(n0 + rA) * 256 + cp0 * 8;
    const uint32_t sA = (uint32_t)rA * LDB + cp0 * 16;

    // ---- fragment (ldmatrix) lane addressing
    const int lane = t & 31, w = t >> 5;
    const int wm = w >> 2, wn = w & 3;
    uint32_t aoff[4], boff[2];
    {
        int ra = wm * 64 + (lane & 7) + ((lane >> 3) & 1) * 8;
        int ac = (lane >> 4) * 16;
#pragma unroll
        for (int i = 0; i < 4; i++) aoff[i] = (uint32_t)(ra + i * 16) * LDB + ac;
        int rb = wn * 32 + (lane & 7) + ((lane >> 4) & 1) * 8;
        int bc = ((lane >> 3) & 1) * 16;
#pragma unroll
        for (int p = 0; p < 2; p++) boff[p] = 2 * MATB + (uint32_t)(rb + p * 16) * LDB + bc;
    }

    float acc[4][4][4];
#pragma unroll
    for (int i = 0; i < 4; i++)
#pragma unroll
        for (int j = 0; j < 4; j++)
#pragma unroll
            for (int p = 0; p < 4; p++) acc[i][j][p] = 0.f;

    // stage chunk -> stage buffer st via cp.async (8 x 16B per thread)
    auto stage_load = [&](int st, int chunk) {
        uint32_t base = sb + st * STAGEB + sA;
        const int go = chunk * 32;
        CP16(base,                (const char*)(pAh + go));
        CP16(base + 16,           (const char*)(pAh + go + 8));
        CP16(base + MATB,         (const char*)(pAl + go));
        CP16(base + MATB + 16,    (const char*)(pAl + go + 8));
        CP16(base + 2 * MATB,     (const char*)(pBh + go));
        CP16(base + 2 * MATB + 16,(const char*)(pBh + go + 8));
        CP16(base + 3 * MATB,     (const char*)(pBl + go));
        CP16(base + 3 * MATB + 16,(const char*)(pBl + go + 8));
        CPCOMMIT();
    };

    stage_load(0, 0);
    stage_load(1, 1);

    for (int c = 0; c < 8; c++) {
        const int st = c & 1;
        if (c < 7) { CPWAIT(1); } else { CPWAIT(0); }
        __syncthreads();
        const uint32_t stb = sb + st * STAGEB;
#pragma unroll
        for (int half = 0; half < 2; half++) {
            const uint32_t ho = half * 32;
            uint32_t bh[8], bl[8];
            ldm4(bh,     stb + boff[0] + ho);
            ldm4(bh + 4, stb + boff[1] + ho);
            ldm4(bl,     stb + boff[0] + MATB + ho);
            ldm4(bl + 4, stb + boff[1] + MATB + ho);
#pragma unroll
            for (int ip = 0; ip < 2; ip++) {
                uint32_t ah0[4], ah1[4], al0[4], al1[4];
                ldm4(ah0, stb + aoff[2 * ip] + ho);
                ldm4(ah1, stb + aoff[2 * ip + 1] + ho);
                ldm4(al0, stb + aoff[2 * ip] + MATB + ho);
                ldm4(al1, stb + aoff[2 * ip + 1] + MATB + ho);
#pragma unroll
                for (int j = 0; j < 4; j++) {
                    mma_bf16(acc[2 * ip][j],     ah0, bh + 2 * j);
                    mma_bf16(acc[2 * ip][j],     ah0, bl + 2 * j);
                    mma_bf16(acc[2 * ip][j],     al0, bh + 2 * j);
                    mma_bf16(acc[2 * ip + 1][j], ah1, bh + 2 * j);
                    mma_bf16(acc[2 * ip + 1][j], ah1, bl + 2 * j);
                    mma_bf16(acc[2 * ip + 1][j], al1, bh + 2 * j);
                }
            }
        }
        __syncthreads();
        if (c + 2 < 8) stage_load(st, c + 2);
    }

    // ---- epilogue: bias add + (optional scatter) store ----
    const int g = lane >> 2, tg = lane & 3;
#pragma unroll
    for (int i = 0; i < 4; i++) {
        int row0 = m0 + wm * 64 + i * 16 + g;
        int row1 = row0 + 8;
        int gm0 = SCATTER ? rowmap(row0) : row0;
        int gm1 = SCATTER ? rowmap(row1) : row1;
        float* p0 = C + (size_t)gm0 * 256;
        float* p1 = C + (size_t)gm1 * 256;
#pragma unroll
        for (int j = 0; j < 4; j++) {
            int col = n0 + wn * 32 + j * 8 + 2 * tg;
            float2 bb = *(const float2*)&bias[col];
            *(float2*)&p0[col] = make_float2(acc[i][j][0] + bb.x, acc[i][j][1] + bb.y);
            *(float2*)&p1[col] = make_float2(acc[i][j][2] + bb.x, acc[i][j][3] + bb.y);
        }
    }
}

// ---------------- attention: one block per (window, head) -------------------
__global__ void __launch_bounds__(256) attn_kernel(const float* __restrict__ ls) {
    __shared__ __align__(16) float QsT[32][68];   // k-major (transposed)
    __shared__ __align__(16) float KsT[32][68];
    __shared__ __align__(16) float Vs[64][36];    // row-major
    __shared__ __align__(16) float Ps[64][65];
    __shared__ float biasH[225];
    __shared__ int cntS[64];

    const int t = threadIdx.x;
    const int h = blockIdx.x;
    const int win = blockIdx.y;
    const size_t base = ((size_t)win * 64) * 256 + h * 32;

    if (t < 225) biasH[t] = g_bias[t * 8 + h];
    {
        int w = win & 63;
        int wy = w >> 3, wx = w & 7;
        if (t < 64) {
            int iy = t >> 3, ix = t & 7;
            int si = wy * 8 + iy, sj = wx * 8 + ix;
            int rh = (si < 56) ? 0 : ((si < 60) ? 1 : 2);
            int rw = (sj < 56) ? 0 : ((sj < 60) ? 1 : 2);
            cntS[t] = rh * 3 + rw;
        }
    }

    // load Q,K transposed + V row-major
#pragma unroll
    for (int ff = 0; ff < 2; ff++) {
        int f = t + ff * 256;
        int row = f >> 3, qd = f & 7;
        size_t ga = base + (size_t)row * 256 + qd * 4;
        float4 qv = *(const float4*)&g_Q[ga];
        float4 kv = *(const float4*)&g_K[ga];
        float4 vv = *(const float4*)&g_V[ga];
#pragma unroll
        for (int u = 0; u < 4; u++) {
            QsT[qd * 4 + u][row] = ((float*)&qv)[u];
            KsT[qd * 4 + u][row] = ((float*)&kv)[u];
        }
        *(float4*)&Vs[row][qd * 4] = vv;
    }
    __syncthreads();

    // cosine normalization of q,k rows
    if (t < 128) {
        int rI = t & 63;
        float(*Mt)[68] = (t < 64) ? QsT : KsT;
        float s = 0.f;
#pragma unroll
        for (int kk = 0; kk < 32; kk++) {
            float v = Mt[kk][rI];
            s += v * v;
        }
        float inv = 1.f / fmaxf(sqrtf(s), 1e-12f);
#pragma unroll
        for (int kk = 0; kk < 32; kk++) Mt[kk][rI] *= inv;
    }
    __syncthreads();

    const float scale = __expf(fminf(ls[h], 4.6051702f));  // exp(min(ls, ln 100))

    // S = qn @ kn^T : 4x4 microtile per thread
    const int rn = t >> 4;
    const int cn = t & 15;
    unsigned long long sp[4][2];
#pragma unroll
    for (int i = 0; i < 4; i++) { sp[i][0] = 0ull; sp[i][1] = 0ull; }
#pragma unroll
    for (int kk = 0; kk < 32; kk++) {
        float4 a = *(const float4*)&QsT[kk][4 * rn];
        ulonglong2 b = *(const ulonglong2*)&KsT[kk][4 * cn];
#pragma unroll
        for (int i = 0; i < 4; i++) {
            unsigned long long ap = pack2(((float*)&a)[i], ((float*)&a)[i]);
            fma2(sp[i][0], ap, b.x);
            fma2(sp[i][1], ap, b.y);
        }
    }

    // scale + bias + shift-mask, then softmax (shfl over the 16-lane row group)
    float sv[4][4];
#pragma unroll
    for (int i = 0; i < 4; i++) {
        float2 e0 = unpack2(sp[i][0]);
        float2 e1 = unpack2(sp[i][1]);
        sv[i][0] = e0.x; sv[i][1] = e0.y; sv[i][2] = e1.x; sv[i][3] = e1.y;
    }
#pragma unroll
    for (int i = 0; i < 4; i++) {
        int n = 4 * rn + i;
        int iy = n >> 3, ix = n & 7;
        int cc = cntS[n];
#pragma unroll
        for (int j = 0; j < 4; j++) {
            int m = 4 * cn + j;
            int jy = m >> 3, jx = m & 7;
            float msk = (cc != cntS[m]) ? -100.f : 0.f;
            sv[i][j] = sv[i][j] * scale + biasH[(iy - jy + 7) * 15 + (ix - jx + 7)] + msk;
        }
    }
#pragma unroll
    for (int i = 0; i < 4; i++) {
        float mx = fmaxf(fmaxf(sv[i][0], sv[i][1]), fmaxf(sv[i][2], sv[i][3]));
        mx = fmaxf(mx, __shfl_xor_sync(0xffffffffu, mx, 1));
        mx = fmaxf(mx, __shfl_xor_sync(0xffffffffu, mx, 2));
        mx = fmaxf(mx, __shfl_xor_sync(0xffffffffu, mx, 4));
        mx = fmaxf(mx, __shfl_xor_sync(0xffffffffu, mx, 8));
        float se = 0.f;
#pragma unroll
        for (int j = 0; j < 4; j++) {
            sv[i][j] = __expf(sv[i][j] - mx);
            se += sv[i][j];
        }
        se += __shfl_xor_sync(0xffffffffu, se, 1);
        se += __shfl_xor_sync(0xffffffffu, se, 2);
        se += __shfl_xor_sync(0xffffffffu, se, 4);
        se += __shfl_xor_sync(0xffffffffu, se, 8);
        float inv = 1.f / se;
        int n = 4 * rn + i;
#pragma unroll
        for (int j = 0; j < 4; j++) Ps[n][4 * cn + j] = sv[i][j] * inv;
    }
    __syncthreads();

    // O = P @ V : each thread owns (row n, 8 of 32 head dims)
    const int n = t >> 2;
    const int q = t & 3;
    unsigned long long ov[4] = {0ull, 0ull, 0ull, 0ull};
#pragma unroll 8
    for (int m = 0; m < 64; m++) {
        float p = Ps[n][m];
        unsigned long long pp = pack2(p, p);
        ulonglong2 v0 = *(const ulonglong2*)&Vs[m][q * 8];
        ulonglong2 v1 = *(const ulonglong2*)&Vs[m][q * 8 + 4];
        fma2(ov[0], pp, v0.x);
        fma2(ov[1], pp, v0.y);
        fma2(ov[2], pp, v1.x);
        fma2(ov[3], pp, v1.y);
    }
    float* po = &g_O[base + (size_t)n * 256 + q * 8];
    *(ulonglong2*)po = make_ulonglong2(ov[0], ov[1]);
    *(ulonglong2*)(po + 4) = make_ulonglong2(ov[2], ov[3]);
}

// ---------------- launch ----------------------------------------------------
extern "C" void kernel_launch(void* const* d_in, const int* in_sizes, int n_in,
                              void* d_out, int out_size) {
    const float* x  = (const float*)d_in[0];
    const float* Wq = (const float*)d_in[1];
    const float* bq = (const float*)d_in[2];
    const float* Wk = (const float*)d_in[3];
    const float* bk = (const float*)d_in[4];
    const float* Wv = (const float*)d_in[5];
    const float* bv = (const float*)d_in[6];
    const float* Wo = (const float*)d_in[7];
    const float* bo = (const float*)d_in[8];
    const float* ls = (const float*)d_in[9];
    const float* w1 = (const float*)d_in[10];
    const float* b1 = (const float*)d_in[11];
    const float* w2 = (const float*)d_in[12];
    float* out = (float*)d_out;

    float *pQ, *pK, *pV, *pO;
    __nv_bfloat16 *pxh, *pxl, *poh, *pol, *pwh, *pwl;
    cudaGetSymbolAddress((void**)&pQ, g_Q);
    cudaGetSymbolAddress((void**)&pK, g_K);
    cudaGetSymbolAddress((void**)&pV, g_V);
    cudaGetSymbolAddress((void**)&pO, g_O);
    cudaGetSymbolAddress((void**)&pxh, g_xh);
    cudaGetSymbolAddress((void**)&pxl, g_xl);
    cudaGetSymbolAddress((void**)&poh, g_oh);
    cudaGetSymbolAddress((void**)&pol, g_ol);
    cudaGetSymbolAddress((void**)&pwh, g_wh);
    cudaGetSymbolAddress((void**)&pwl, g_wl);

    cudaFuncSetAttribute(gemm_mma2<true, false>,
                         cudaFuncAttributeMaxDynamicSharedMemorySize, GSMEM);
    cudaFuncSetAttribute(gemm_mma2<false, true>,
                         cudaFuncAttributeMaxDynamicSharedMemorySize, GSMEM);

    cpb_kernel<<<8, 256>>>(w1, b1, w2);

    const int xn4 = TOK * CD / 4;
    const int wn4 = CD * CD / 4;
    split_kernel<<<xn4 / 256, 256>>>(x, pxh, pxl, xn4);
    split_kernel<<<wn4 / 256, 256>>>(Wq, pwh + 0 * CD * CD, pwl + 0 * CD * CD, wn4);
    split_kernel<<<wn4 / 256, 256>>>(Wk, pwh + 1 * CD * CD, pwl + 1 * CD * CD, wn4);
    split_kernel<<<wn4 / 256, 256>>>(Wv, pwh + 2 * CD * CD, pwl + 2 * CD * CD, wn4);
    split_kernel<<<wn4 / 256, 256>>>(Wo, pwh + 3 * CD * CD, pwl + 3 * CD * CD, wn4);

    dim3 gg(2, 1024);
    gemm_mma2<true, false><<<gg, 256, GSMEM>>>(pxh, pxl, pwh + 0 * CD * CD, pwl + 0 * CD * CD, bq, pQ);
    gemm_mma2<true, false><<<gg, 256, GSMEM>>>(pxh, pxl, pwh + 1 * CD * CD, pwl + 1 * CD * CD, bk, pK);
    gemm_mma2<true, false><<<gg, 256, GSMEM>>>(pxh, pxl, pwh + 2 * CD * CD, pwl + 2 * CD * CD, bv, pV);

    attn_kernel<<<dim3(8, 2048), 256>>>(ls);

    split_kernel<<<xn4 / 256, 256>>>(pO, poh, pol, xn4);
    gemm_mma2<false, true><<<gg, 256, GSMEM>>>(poh, pol, pwh + 3 * CD * CD, pwl + 3 * CD * CD, bo, out);
}

// round 6
// speedup vs baseline: 1.7955x; 1.2408x over previous
#include <cuda_runtime.h>
#include <cuda_bf16.h>
#include <cstdint>

#define TOK 131072   // B*H*W = 32*64*64 tokens
#define CD  256

// ---------------- scratch (device globals; no allocations allowed) ----------
__device__ float g_Q[TOK * CD];
__device__ float g_K[TOK * CD];
__device__ float g_V[TOK * CD];
__device__ float g_bias[225 * 8];
__device__ __nv_bfloat16 g_xh[TOK * CD], g_xl[TOK * CD];
__device__ __nv_bfloat16 g_oh[TOK * CD], g_ol[TOK * CD];
__device__ __nv_bfloat16 g_wh[4 * CD * CD], g_wl[4 * CD * CD];

// ---------------- helpers ----------------------------------------------------
__device__ __forceinline__ uint32_t smem_u32(const void* p) {
    uint32_t a;
    asm("{ .reg .u64 t; cvta.to.shared.u64 t, %1; cvt.u32.u64 %0, t; }"
        : "=r"(a) : "l"(p));
    return a;
}

// token index (window order) -> row in the [B,H,W] image (shift+partition map)
__device__ __forceinline__ int rowmap(int m) {
    int win = m >> 6, n = m & 63;
    int b = win >> 6, w = win & 63;
    int wy = w >> 3, wx = w & 7;
    int iy = n >> 3, ix = n & 7;
    int gi = (wy * 8 + iy + 4) & 63;
    int gj = (wx * 8 + ix + 4) & 63;
    return (b * 64 + gi) * 64 + gj;
}

// bf16 split helpers
__device__ __forceinline__ uint32_t cvt_hi2(float a, float b, float& ra, float& rb) {
    __nv_bfloat16 ha = __float2bfloat16_rn(a), hb = __float2bfloat16_rn(b);
    ra = a - __bfloat162float(ha);
    rb = b - __bfloat162float(hb);
    __nv_bfloat162 p = __halves2bfloat162(ha, hb);
    return *(uint32_t*)&p;
}
__device__ __forceinline__ uint32_t cvt2(float a, float b) {
    __nv_bfloat162 p = __halves2bfloat162(__float2bfloat16_rn(a), __float2bfloat16_rn(b));
    return *(uint32_t*)&p;
}

__device__ __forceinline__ void mma_bf16(float* d, const uint32_t* a, const uint32_t* b) {
    asm volatile(
        "mma.sync.aligned.m16n8k16.row.col.f32.bf16.bf16.f32 "
        "{%0,%1,%2,%3}, {%4,%5,%6,%7}, {%8,%9}, {%0,%1,%2,%3};"
        : "+f"(d[0]), "+f"(d[1]), "+f"(d[2]), "+f"(d[3])
        : "r"(a[0]), "r"(a[1]), "r"(a[2]), "r"(a[3]), "r"(b[0]), "r"(b[1]));
}
__device__ __forceinline__ void ldm4(uint32_t* r, uint32_t addr) {
    asm volatile("ldmatrix.sync.aligned.m8n8.x4.shared.b16 {%0,%1,%2,%3}, [%4];"
                 : "=r"(r[0]), "=r"(r[1]), "=r"(r[2]), "=r"(r[3]) : "r"(addr));
}
#define CP16(s, g) asm volatile("cp.async.cg.shared.global [%0], [%1], 16;" :: "r"(s), "l"(g))
#define CPCOMMIT() asm volatile("cp.async.commit_group;" ::: "memory")
#define CPWAIT(n)  asm volatile("cp.async.wait_group %0;" :: "n"(n) : "memory")

// ---------------- fp32 -> bf16 hi/lo split pass ------------------------------
__global__ void split_kernel(const float* __restrict__ src, __nv_bfloat16* __restrict__ hi,
                             __nv_bfloat16* __restrict__ lo, int n4) {
    int i = blockIdx.x * blockDim.x + threadIdx.x;
    if (i >= n4) return;
    float4 v = ((const float4*)src)[i];
    __nv_bfloat16 h0 = __float2bfloat16_rn(v.x), h1 = __float2bfloat16_rn(v.y);
    __nv_bfloat16 h2 = __float2bfloat16_rn(v.z), h3 = __float2bfloat16_rn(v.w);
    __nv_bfloat16 l0 = __float2bfloat16_rn(v.x - __bfloat162float(h0));
    __nv_bfloat16 l1 = __float2bfloat16_rn(v.y - __bfloat162float(h1));
    __nv_bfloat16 l2 = __float2bfloat16_rn(v.z - __bfloat162float(h2));
    __nv_bfloat16 l3 = __float2bfloat16_rn(v.w - __bfloat162float(h3));
    ((__nv_bfloat162*)hi)[2 * i]     = __halves2bfloat162(h0, h1);
    ((__nv_bfloat162*)hi)[2 * i + 1] = __halves2bfloat162(h2, h3);
    ((__nv_bfloat162*)lo)[2 * i]     = __halves2bfloat162(l0, l1);
    ((__nv_bfloat162*)lo)[2 * i + 1] = __halves2bfloat162(l2, l3);
}

// ---------------- CPB-MLP (parallel over heads) ------------------------------
__device__ __forceinline__ float cpb_coord(int a) {
    float r = (float)(a - 7);
    float v = r * (8.0f / 7.0f);
    float s = (v > 0.f) ? 1.f : ((v < 0.f) ? -1.f : 0.f);
    return s * log2f(fabsf(v) + 1.f) * (1.0f / 3.0f);
}

__global__ void cpb_kernel(const float* __restrict__ w1, const float* __restrict__ b1,
                           const float* __restrict__ w2) {
    int t = threadIdx.x;
    int h = blockIdx.x;
    if (t >= 225) return;
    float ta = cpb_coord(t / 15);
    float tb = cpb_coord(t % 15);
    float acc = 0.f;
    for (int j = 0; j < 512; j++) {
        float hd = ta * w1[2 * j] + tb * w1[2 * j + 1] + b1[j];
        hd = fmaxf(hd, 0.f);
        acc += hd * w2[h * 512 + j];
    }
    g_bias[t * 8 + h] = 16.f / (1.f + expf(-acc));
}

// ---------------- split-bf16 mma GEMM, cp.async + ldmatrix -------------------
#define LDBROW 80                 // bytes per smem row (32 bf16 + 16B pad)
#define MATB   (128 * LDBROW)     // 10240
#define STAGEB (4 * MATB)         // 40960: Ah | Al | Bh | Bl
#define GSMEM  (2 * STAGEB)       // 81920

template <bool GATHER, bool SCATTER>
__global__ void __launch_bounds__(256, 2) gemm_mma2(
    const __nv_bfloat16* __restrict__ Ah_, const __nv_bfloat16* __restrict__ Al_,
    const __nv_bfloat16* __restrict__ Bh_, const __nv_bfloat16* __restrict__ Bl_,
    const float* __restrict__ bias, float* __restrict__ C) {
    extern __shared__ char sm[];
    const uint32_t sb = smem_u32(sm);
    const int t = threadIdx.x;
    const int n0 = blockIdx.x * 128, m0 = blockIdx.y * 128;

    const int rA = t >> 1;
    const int cp0 = (t & 1) * 2;
    int garow = m0 + rA;
    if (GATHER) garow = rowmap(garow);
    const __nv_bfloat16* pAh = Ah_ + (size_t)garow * 256 + cp0 * 8;
    const __nv_bfloat16* pAl = Al_ + (size_t)garow * 256 + cp0 * 8;
    const __nv_bfloat16* pBh = Bh_ + (size_t)(n0 + rA) * 256 + cp0 * 8;
    const __nv_bfloat16* pBl = Bl_ + (size_t)(n0 + rA) * 256 + cp0 * 8;
    const uint32_t sA = (uint32_t)rA * LDBROW + cp0 * 16;

    const int lane = t & 31, w = t >> 5;
    const int wm = w >> 2, wn = w & 3;
    uint32_t aoff[4], boff[2];
    {
        int ra = wm * 64 + (lane & 7) + ((lane >> 3) & 1) * 8;
        int ac = (lane >> 4) * 16;
#pragma unroll
        for (int i = 0; i < 4; i++) aoff[i] = (uint32_t)(ra + i * 16) * LDBROW + ac;
        int rb = wn * 32 + (lane & 7) + ((lane >> 4) & 1) * 8;
        int bc = ((lane >> 3) & 1) * 16;
#pragma unroll
        for (int p = 0; p < 2; p++) boff[p] = 2 * MATB + (uint32_t)(rb + p * 16) * LDBROW + bc;
    }

    float acc[4][4][4];
#pragma unroll
    for (int i = 0; i < 4; i++)
#pragma unroll
        for (int j = 0; j < 4; j++)
#pragma unroll
            for (int p = 0; p < 4; p++) acc[i][j][p] = 0.f;

    auto stage_load = [&](int st, int chunk) {
        uint32_t base = sb + st * STAGEB + sA;
        const int go = chunk * 32;
        CP16(base,                (const char*)(pAh + go));
        CP16(base + 16,           (const char*)(pAh + go + 8));
        CP16(base + MATB,         (const char*)(pAl + go));
        CP16(base + MATB + 16,    (const char*)(pAl + go + 8));
        CP16(base + 2 * MATB,     (const char*)(pBh + go));
        CP16(base + 2 * MATB + 16,(const char*)(pBh + go + 8));
        CP16(base + 3 * MATB,     (const char*)(pBl + go));
        CP16(base + 3 * MATB + 16,(const char*)(pBl + go + 8));
        CPCOMMIT();
    };

    stage_load(0, 0);
    stage_load(1, 1);

    for (int c = 0; c < 8; c++) {
        const int st = c & 1;
        if (c < 7) { CPWAIT(1); } else { CPWAIT(0); }
        __syncthreads();
        const uint32_t stb = sb + st * STAGEB;
#pragma unroll
        for (int half = 0; half < 2; half++) {
            const uint32_t ho = half * 32;
            uint32_t bh[8], bl[8];
            ldm4(bh,     stb + boff[0] + ho);
            ldm4(bh + 4, stb + boff[1] + ho);
            ldm4(bl,     stb + boff[0] + MATB + ho);
            ldm4(bl + 4, stb + boff[1] + MATB + ho);
#pragma unroll
            for (int ip = 0; ip < 2; ip++) {
                uint32_t ah0[4], ah1[4], al0[4], al1[4];
                ldm4(ah0, stb + aoff[2 * ip] + ho);
                ldm4(ah1, stb + aoff[2 * ip + 1] + ho);
                ldm4(al0, stb + aoff[2 * ip] + MATB + ho);
                ldm4(al1, stb + aoff[2 * ip + 1] + MATB + ho);
#pragma unroll
                for (int j = 0; j < 4; j++) {
                    mma_bf16(acc[2 * ip][j],     ah0, bh + 2 * j);
                    mma_bf16(acc[2 * ip][j],     ah0, bl + 2 * j);
                    mma_bf16(acc[2 * ip][j],     al0, bh + 2 * j);
                    mma_bf16(acc[2 * ip + 1][j], ah1, bh + 2 * j);
                    mma_bf16(acc[2 * ip + 1][j], ah1, bl + 2 * j);
                    mma_bf16(acc[2 * ip + 1][j], al1, bh + 2 * j);
                }
            }
        }
        __syncthreads();
        if (c + 2 < 8) stage_load(st, c + 2);
    }

    const int g = lane >> 2, tg = lane & 3;
#pragma unroll
    for (int i = 0; i < 4; i++) {
        int row0 = m0 + wm * 64 + i * 16 + g;
        int row1 = row0 + 8;
        int gm0 = SCATTER ? rowmap(row0) : row0;
        int gm1 = SCATTER ? rowmap(row1) : row1;
        float* p0 = C + (size_t)gm0 * 256;
        float* p1 = C + (size_t)gm1 * 256;
#pragma unroll
        for (int j = 0; j < 4; j++) {
            int col = n0 + wn * 32 + j * 8 + 2 * tg;
            float2 bb = *(const float2*)&bias[col];
            *(float2*)&p0[col] = make_float2(acc[i][j][0] + bb.x, acc[i][j][1] + bb.y);
            *(float2*)&p1[col] = make_float2(acc[i][j][2] + bb.x, acc[i][j][3] + bb.y);
        }
    }
}

// ---------------- tensor-core attention --------------------------------------
// Block = (window, head-pair). 8 warps = 2 heads x 4 M-quarters (16 rows each).
// QK^T and PV both as 3-term split-bf16 mma; softmax in C-fragments; P never
// hits smem (C-fragment -> A-fragment repack). O written as bf16 hi/lo.
#define AQS  80                   // Q/K smem row bytes (32 bf16 + pad)
#define AQHS (64 * AQS)           // 5120 per head
#define AVS  144                  // Vt smem row bytes (64 bf16 + pad)
#define AVHS (32 * AVS)           // 4608 per head
#define OF_QH 0
#define OF_QL 10240
#define OF_KH 20480
#define OF_KL 30720
#define OF_VH 40960
#define OF_VL 50176
#define OF_TAB 59392              // u16[64*64]
#define OF_BF 67584               // float[2][225]
#define ATTN_SMEM 69632

__global__ void __launch_bounds__(256, 2) attn_mma(const float* __restrict__ ls) {
    extern __shared__ char sm[];
    const uint32_t sb = smem_u32(sm);
    const int t = threadIdx.x;
    const int win = blockIdx.y;
    const int hp = blockIdx.x;            // heads hp*2, hp*2+1
    const int wloc = win & 63;
    const int wy = wloc >> 3, wx = wloc & 7;

    float* biasF = (float*)(sm + OF_BF);
    uint16_t* tab = (uint16_t*)(sm + OF_TAB);

    if (t < 225) {
        biasF[t]       = g_bias[t * 8 + hp * 2];
        biasF[225 + t] = g_bias[t * 8 + hp * 2 + 1];
    }
    // combined bias-index + mask table (window-dependent)
#pragma unroll
    for (int e = t; e < 4096; e += 256) {
        int n = e >> 6, m = e & 63;
        int iy = n >> 3, ix = n & 7, jy = m >> 3, jx = m & 7;
        int idx = (iy - jy + 7) * 15 + (ix - jx + 7);
        int si = wy * 8 + iy, sj = wx * 8 + ix;
        int cn = ((si < 56) ? 0 : ((si < 60) ? 1 : 2)) * 3 + ((sj < 56) ? 0 : ((sj < 60) ? 1 : 2));
        int sm2 = wy * 8 + jy, sn2 = wx * 8 + jx;
        int cm = ((sm2 < 56) ? 0 : ((sm2 < 60) ? 1 : 2)) * 3 + ((sn2 < 56) ? 0 : ((sn2 < 60) ? 1 : 2));
        tab[e] = (uint16_t)(idx | ((cn != cm) ? 256 : 0));
    }

    // ---- load + normalize + split Q (t<128) / K (t>=128); V by t<128 ----
    const size_t gwin = (size_t)win * 64 * 256 + hp * 64;
    {
        int r = t & 127;
        int hh2 = r >> 6, tok = r & 63;
        const float* src = (t < 128) ? g_Q : g_K;
        const int ofh = (t < 128) ? OF_QH : OF_KH;
        size_t ga = gwin + (size_t)tok * 256 + hh2 * 32;
        float v[32];
        float ss = 0.f;
#pragma unroll
        for (int i = 0; i < 8; i++) {
            float4 q4 = *(const float4*)&src[ga + i * 4];
            v[4 * i] = q4.x; v[4 * i + 1] = q4.y; v[4 * i + 2] = q4.z; v[4 * i + 3] = q4.w;
            ss += q4.x * q4.x + q4.y * q4.y + q4.z * q4.z + q4.w * q4.w;
        }
        float inv = 1.f / fmaxf(sqrtf(ss), 1e-12f);
        uint32_t* dh = (uint32_t*)(sm + ofh + hh2 * AQHS + tok * AQS);
        uint32_t* dl = (uint32_t*)(sm + ofh + 10240 + hh2 * AQHS + tok * AQS);
#pragma unroll
        for (int i = 0; i < 16; i++) {
            float a = v[2 * i] * inv, b = v[2 * i + 1] * inv;
            float ra, rb;
            dh[i] = cvt_hi2(a, b, ra, rb);
            dl[i] = cvt2(ra, rb);
        }
    }
    if (t < 128) {  // V row -> transposed hi/lo
        int hh2 = t >> 6, tok = t & 63;
        size_t ga = gwin + (size_t)tok * 256 + hh2 * 32;
        char* vh = sm + OF_VH + hh2 * AVHS;
        char* vl = sm + OF_VL + hh2 * AVHS;
#pragma unroll
        for (int i = 0; i < 8; i++) {
            float4 q4 = *(const float4*)&g_V[ga + i * 4];
            float vv[4] = {q4.x, q4.y, q4.z, q4.w};
#pragma unroll
            for (int u = 0; u < 4; u++) {
                int d = 4 * i + u;
                __nv_bfloat16 hb = __float2bfloat16_rn(vv[u]);
                __nv_bfloat16 lb = __float2bfloat16_rn(vv[u] - __bfloat162float(hb));
                *(__nv_bfloat16*)(vh + d * AVS + tok * 2) = hb;
                *(__nv_bfloat16*)(vl + d * AVS + tok * 2) = lb;
            }
        }
    }
    __syncthreads();

    // ---- per-warp mma compute ----
    const int lane = t & 31, w = t >> 5;
    const int hh = w >> 2, wm = w & 3;
    const int head = hp * 2 + hh;
    const float scale = __expf(fminf(ls[head], 4.6051702f));
    const int g = lane >> 2, tg = lane & 3;

    const uint32_t qb = sb + OF_QH + hh * AQHS;
    const uint32_t kb = sb + OF_KH + hh * AQHS;

    uint32_t qh[2][4], ql[2][4];
    {
        int row = wm * 16 + (lane & 7) + ((lane >> 3) & 1) * 8;
        uint32_t col = (lane >> 4) * 16;
        uint32_t a0 = qb + (uint32_t)row * AQS + col;
        ldm4(qh[0], a0); ldm4(qh[1], a0 + 32);
        ldm4(ql[0], a0 + 10240); ldm4(ql[1], a0 + 10240 + 32);
    }
    float acc[8][4];
#pragma unroll
    for (int i = 0; i < 8; i++)
#pragma unroll
        for (int p = 0; p < 4; p++) acc[i][p] = 0.f;

    {
        int rowb = (lane & 7) + ((lane >> 4) & 1) * 8;
        uint32_t colb = ((lane >> 3) & 1) * 16;
#pragma unroll
        for (int np = 0; np < 4; np++) {
            uint32_t b0 = kb + (uint32_t)(np * 16 + rowb) * AQS + colb;
#pragma unroll
            for (int kt = 0; kt < 2; kt++) {
                uint32_t bh[4], bl[4];
                ldm4(bh, b0 + kt * 32);
                ldm4(bl, b0 + kt * 32 + 10240);
                mma_bf16(acc[2 * np],     qh[kt], bh);
                mma_bf16(acc[2 * np],     qh[kt], bl);
                mma_bf16(acc[2 * np],     ql[kt], bh);
                mma_bf16(acc[2 * np + 1], qh[kt], bh + 2);
                mma_bf16(acc[2 * np + 1], qh[kt], bl + 2);
                mma_bf16(acc[2 * np + 1], ql[kt], bh + 2);
            }
        }
    }

    // ---- scale + bias/mask + softmax in fragments ----
    const int n0r = wm * 16 + g;
    const int n1r = n0r + 8;
    const float* bf = biasF + hh * 225;
#pragma unroll
    for (int nt = 0; nt < 8; nt++) {
#pragma unroll
        for (int c = 0; c < 2; c++) {
            int m = nt * 8 + 2 * tg + c;
            uint16_t e0 = tab[n0r * 64 + m];
            acc[nt][c] = acc[nt][c] * scale + bf[e0 & 255] - 100.f * (float)(e0 >> 8);
            uint16_t e1 = tab[n1r * 64 + m];
            acc[nt][2 + c] = acc[nt][2 + c] * scale + bf[e1 & 255] - 100.f * (float)(e1 >> 8);
        }
    }
    float mx0 = -1e30f, mx1 = -1e30f;
#pragma unroll
    for (int nt = 0; nt < 8; nt++) {
        mx0 = fmaxf(mx0, fmaxf(acc[nt][0], acc[nt][1]));
        mx1 = fmaxf(mx1, fmaxf(acc[nt][2], acc[nt][3]));
    }
    mx0 = fmaxf(mx0, __shfl_xor_sync(0xffffffffu, mx0, 1));
    mx0 = fmaxf(mx0, __shfl_xor_sync(0xffffffffu, mx0, 2));
    mx1 = fmaxf(mx1, __shfl_xor_sync(0xffffffffu, mx1, 1));
    mx1 = fmaxf(mx1, __shfl_xor_sync(0xffffffffu, mx1, 2));
    float s0 = 0.f, s1 = 0.f;
#pragma unroll
    for (int nt = 0; nt < 8; nt++) {
        acc[nt][0] = __expf(acc[nt][0] - mx0); s0 += acc[nt][0];
        acc[nt][1] = __expf(acc[nt][1] - mx0); s0 += acc[nt][1];
        acc[nt][2] = __expf(acc[nt][2] - mx1); s1 += acc[nt][2];
        acc[nt][3] = __expf(acc[nt][3] - mx1); s1 += acc[nt][3];
    }
    s0 += __shfl_xor_sync(0xffffffffu, s0, 1);
    s0 += __shfl_xor_sync(0xffffffffu, s0, 2);
    s1 += __shfl_xor_sync(0xffffffffu, s1, 1);
    s1 += __shfl_xor_sync(0xffffffffu, s1, 2);
    float i0 = 1.f / s0, i1 = 1.f / s1;
#pragma unroll
    for (int nt = 0; nt < 8; nt++) {
        acc[nt][0] *= i0; acc[nt][1] *= i0; acc[nt][2] *= i1; acc[nt][3] *= i1;
    }

    // ---- PV: A from P fragments (register repack), B = Vt from smem ----
    float acco[4][4];
#pragma unroll
    for (int p = 0; p < 4; p++)
#pragma unroll
        for (int c = 0; c < 4; c++) acco[p][c] = 0.f;

    const uint32_t vb = sb + OF_VH + hh * AVHS;
    const int rowv = (lane & 7) + ((lane >> 4) & 1) * 8;
    const uint32_t colv = ((lane >> 3) & 1) * 16;
#pragma unroll
    for (int j = 0; j < 4; j++) {
        uint32_t ah[4], al[4];
        float ra, rb;
        ah[0] = cvt_hi2(acc[2 * j][0],     acc[2 * j][1],     ra, rb); al[0] = cvt2(ra, rb);
        ah[1] = cvt_hi2(acc[2 * j][2],     acc[2 * j][3],     ra, rb); al[1] = cvt2(ra, rb);
        ah[2] = cvt_hi2(acc[2 * j + 1][0], acc[2 * j + 1][1], ra, rb); al[2] = cvt2(ra, rb);
        ah[3] = cvt_hi2(acc[2 * j + 1][2], acc[2 * j + 1][3], ra, rb); al[3] = cvt2(ra, rb);

        uint32_t va = vb + (uint32_t)rowv * AVS + colv + j * 32;
        uint32_t vh0[4], vh1[4], vl0[4], vl1[4];
        ldm4(vh0, va);
        ldm4(vh1, va + 16 * AVS);
        ldm4(vl0, va + 9216);
        ldm4(vl1, va + 9216 + 16 * AVS);

        mma_bf16(acco[0], ah, vh0);     mma_bf16(acco[0], al, vh0);     mma_bf16(acco[0], ah, vl0);
        mma_bf16(acco[1], ah, vh0 + 2); mma_bf16(acco[1], al, vh0 + 2); mma_bf16(acco[1], ah, vl0 + 2);
        mma_bf16(acco[2], ah, vh1);     mma_bf16(acco[2], al, vh1);     mma_bf16(acco[2], ah, vl1);
        mma_bf16(acco[3], ah, vh1 + 2); mma_bf16(acco[3], al, vh1 + 2); mma_bf16(acco[3], ah, vl1 + 2);
    }

    // ---- store O as bf16 hi/lo (feeds the final GEMM directly) ----
    const size_t obase = (size_t)win * 64 * 256 + head * 32;
    const int tok0 = wm * 16 + g, tok1 = tok0 + 8;
#pragma unroll
    for (int p = 0; p < 4; p++) {
        int d = p * 8 + 2 * tg;
        float ra, rb;
        uint32_t h01 = cvt_hi2(acco[p][0], acco[p][1], ra, rb);
        uint32_t l01 = cvt2(ra, rb);
        *(uint32_t*)&g_oh[obase + (size_t)tok0 * 256 + d] = h01;
        *(uint32_t*)&g_ol[obase + (size_t)tok0 * 256 + d] = l01;
        uint32_t h23 = cvt_hi2(acco[p][2], acco[p][3], ra, rb);
        uint32_t l23 = cvt2(ra, rb);
        *(uint32_t*)&g_oh[obase + (size_t)tok1 * 256 + d] = h23;
        *(uint32_t*)&g_ol[obase + (size_t)tok1 * 256 + d] = l23;
    }
}

// ---------------- launch ----------------------------------------------------
extern "C" void kernel_launch(void* const* d_in, const int* in_sizes, int n_in,
                              void* d_out, int out_size) {
    const float* x  = (const float*)d_in[0];
    const float* Wq = (const float*)d_in[1];
    const float* bq = (const float*)d_in[2];
    const float* Wk = (const float*)d_in[3];
    const float* bk = (const float*)d_in[4];
    const float* Wv = (const float*)d_in[5];
    const float* bv = (const float*)d_in[6];
    const float* Wo = (const float*)d_in[7];
    const float* bo = (const float*)d_in[8];
    const float* ls = (const float*)d_in[9];
    const float* w1 = (const float*)d_in[10];
    const float* b1 = (const float*)d_in[11];
    const float* w2 = (const float*)d_in[12];
    float* out = (float*)d_out;

    float *pQ, *pK, *pV;
    __nv_bfloat16 *pxh, *pxl, *poh, *pol, *pwh, *pwl;
    cudaGetSymbolAddress((void**)&pQ, g_Q);
    cudaGetSymbolAddress((void**)&pK, g_K);
    cudaGetSymbolAddress((void**)&pV, g_V);
    cudaGetSymbolAddress((void**)&pxh, g_xh);
    cudaGetSymbolAddress((void**)&pxl, g_xl);
    cudaGetSymbolAddress((void**)&poh, g_oh);
    cudaGetSymbolAddress((void**)&pol, g_ol);
    cudaGetSymbolAddress((void**)&pwh, g_wh);
    cudaGetSymbolAddress((void**)&pwl, g_wl);

    cudaFuncSetAttribute(gemm_mma2<true, false>,
                         cudaFuncAttributeMaxDynamicSharedMemorySize, GSMEM);
    cudaFuncSetAttribute(gemm_mma2<false, true>,
                         cudaFuncAttributeMaxDynamicSharedMemorySize, GSMEM);
    cudaFuncSetAttribute(attn_mma,
                         cudaFuncAttributeMaxDynamicSharedMemorySize, ATTN_SMEM);

    cpb_kernel<<<8, 256>>>(w1, b1, w2);

    const int xn4 = TOK * CD / 4;
    const int wn4 = CD * CD / 4;
    split_kernel<<<xn4 / 256, 256>>>(x, pxh, pxl, xn4);
    split_kernel<<<wn4 / 256, 256>>>(Wq, pwh + 0 * CD * CD, pwl + 0 * CD * CD, wn4);
    split_kernel<<<wn4 / 256, 256>>>(Wk, pwh + 1 * CD * CD, pwl + 1 * CD * CD, wn4);
    split_kernel<<<wn4 / 256, 256>>>(Wv, pwh + 2 * CD * CD, pwl + 2 * CD * CD, wn4);
    split_kernel<<<wn4 / 256, 256>>>(Wo, pwh + 3 * CD * CD, pwl + 3 * CD * CD, wn4);

    dim3 gg(2, 1024);
    gemm_mma2<true, false><<<gg, 256, GSMEM>>>(pxh, pxl, pwh + 0 * CD * CD, pwl + 0 * CD * CD, bq, pQ);
    gemm_mma2<true, false><<<gg, 256, GSMEM>>>(pxh, pxl, pwh + 1 * CD * CD, pwl + 1 * CD * CD, bk, pK);
    gemm_mma2<true, false><<<gg, 256, GSMEM>>>(pxh, pxl, pwh + 2 * CD * CD, pwl + 2 * CD * CD, bv, pV);

    attn_mma<<<dim3(4, 2048), 256, ATTN_SMEM>>>(ls);

    gemm_mma2<false, true><<<gg, 256, GSMEM>>>(poh, pol, pwh + 3 * CD * CD, pwl + 3 * CD * CD, bo, out);
}

// round 7
// speedup vs baseline: 1.8505x; 1.0306x over previous
#include <cuda_runtime.h>
#include <cuda_bf16.h>
#include <cstdint>

#define TOK 131072   // B*H*W = 32*64*64 tokens
#define CD  256

// ---------------- scratch (device globals; no allocations allowed) ----------
__device__ float g_bias[225 * 8];
__device__ __nv_bfloat16 g_xh[TOK * CD], g_xl[TOK * CD];
__device__ __nv_bfloat16 g_qh[TOK * CD], g_ql[TOK * CD];
__device__ __nv_bfloat16 g_kh[TOK * CD], g_kl[TOK * CD];
__device__ __nv_bfloat16 g_vh[TOK * CD], g_vl[TOK * CD];
__device__ __nv_bfloat16 g_oh[TOK * CD], g_ol[TOK * CD];
__device__ __nv_bfloat16 g_wh[4 * CD * CD], g_wl[4 * CD * CD];
__device__ __align__(16) uint16_t g_tabs[64 * 4096];

// ---------------- helpers ----------------------------------------------------
__device__ __forceinline__ uint32_t smem_u32(const void* p) {
    uint32_t a;
    asm("{ .reg .u64 t; cvta.to.shared.u64 t, %1; cvt.u32.u64 %0, t; }"
        : "=r"(a) : "l"(p));
    return a;
}

// token index (window order) -> row in the [B,H,W] image (shift+partition map)
__device__ __forceinline__ int rowmap(int m) {
    int win = m >> 6, n = m & 63;
    int b = win >> 6, w = win & 63;
    int wy = w >> 3, wx = w & 7;
    int iy = n >> 3, ix = n & 7;
    int gi = (wy * 8 + iy + 4) & 63;
    int gj = (wx * 8 + ix + 4) & 63;
    return (b * 64 + gi) * 64 + gj;
}

// bf16 split helpers
__device__ __forceinline__ uint32_t cvt_hi2(float a, float b, float& ra, float& rb) {
    __nv_bfloat16 ha = __float2bfloat16_rn(a), hb = __float2bfloat16_rn(b);
    ra = a - __bfloat162float(ha);
    rb = b - __bfloat162float(hb);
    __nv_bfloat162 p = __halves2bfloat162(ha, hb);
    return *(uint32_t*)&p;
}
__device__ __forceinline__ uint32_t cvt2(float a, float b) {
    __nv_bfloat162 p = __halves2bfloat162(__float2bfloat16_rn(a), __float2bfloat16_rn(b));
    return *(uint32_t*)&p;
}

__device__ __forceinline__ void mma_bf16(float* d, const uint32_t* a, const uint32_t* b) {
    asm volatile(
        "mma.sync.aligned.m16n8k16.row.col.f32.bf16.bf16.f32 "
        "{%0,%1,%2,%3}, {%4,%5,%6,%7}, {%8,%9}, {%0,%1,%2,%3};"
        : "+f"(d[0]), "+f"(d[1]), "+f"(d[2]), "+f"(d[3])
        : "r"(a[0]), "r"(a[1]), "r"(a[2]), "r"(a[3]), "r"(b[0]), "r"(b[1]));
}
__device__ __forceinline__ void ldm4(uint32_t* r, uint32_t addr) {
    asm volatile("ldmatrix.sync.aligned.m8n8.x4.shared.b16 {%0,%1,%2,%3}, [%4];"
                 : "=r"(r[0]), "=r"(r[1]), "=r"(r[2]), "=r"(r[3]) : "r"(addr));
}
__device__ __forceinline__ void ldm4t(uint32_t* r, uint32_t addr) {
    asm volatile("ldmatrix.sync.aligned.m8n8.x4.trans.shared.b16 {%0,%1,%2,%3}, [%4];"
                 : "=r"(r[0]), "=r"(r[1]), "=r"(r[2]), "=r"(r[3]) : "r"(addr));
}
#define CP16(s, g) asm volatile("cp.async.cg.shared.global [%0], [%1], 16;" :: "r"(s), "l"(g))
#define CPCOMMIT() asm volatile("cp.async.commit_group;" ::: "memory")
#define CPWAIT(n)  asm volatile("cp.async.wait_group %0;" :: "n"(n) : "memory")

// ---------------- fp32 -> bf16 hi/lo split pass ------------------------------
__global__ void split_kernel(const float* __restrict__ src, __nv_bfloat16* __restrict__ hi,
                             __nv_bfloat16* __restrict__ lo, int n4) {
    int i = blockIdx.x * blockDim.x + threadIdx.x;
    if (i >= n4) return;
    float4 v = ((const float4*)src)[i];
    float r0, r1, r2, r3;
    uint32_t h01 = cvt_hi2(v.x, v.y, r0, r1);
    uint32_t h23 = cvt_hi2(v.z, v.w, r2, r3);
    ((uint32_t*)hi)[2 * i] = h01;
    ((uint32_t*)hi)[2 * i + 1] = h23;
    ((uint32_t*)lo)[2 * i] = cvt2(r0, r1);
    ((uint32_t*)lo)[2 * i + 1] = cvt2(r2, r3);
}

// ---------------- CPB-MLP (parallel over heads) ------------------------------
__device__ __forceinline__ float cpb_coord(int a) {
    float r = (float)(a - 7);
    float v = r * (8.0f / 7.0f);
    float s = (v > 0.f) ? 1.f : ((v < 0.f) ? -1.f : 0.f);
    return s * log2f(fabsf(v) + 1.f) * (1.0f / 3.0f);
}

__global__ void cpb_kernel(const float* __restrict__ w1, const float* __restrict__ b1,
                           const float* __restrict__ w2) {
    int t = threadIdx.x;
    int h = blockIdx.x;
    if (t >= 225) return;
    float ta = cpb_coord(t / 15);
    float tb = cpb_coord(t % 15);
    float acc = 0.f;
    for (int j = 0; j < 512; j++) {
        float hd = ta * w1[2 * j] + tb * w1[2 * j + 1] + b1[j];
        hd = fmaxf(hd, 0.f);
        acc += hd * w2[h * 512 + j];
    }
    g_bias[t * 8 + h] = 16.f / (1.f + expf(-acc));
}

// ---------------- per-window-position bias-index + mask tables ---------------
__global__ void tab_kernel() {
    int wloc = blockIdx.x;
    int wy = wloc >> 3, wx = wloc & 7;
    for (int e = threadIdx.x; e < 4096; e += 256) {
        int n = e >> 6, m = e & 63;
        int iy = n >> 3, ix = n & 7, jy = m >> 3, jx = m & 7;
        int idx = (iy - jy + 7) * 15 + (ix - jx + 7);
        int si = wy * 8 + iy, sj = wx * 8 + ix;
        int cn = ((si < 56) ? 0 : ((si < 60) ? 1 : 2)) * 3 +
                 ((sj < 56) ? 0 : ((sj < 60) ? 1 : 2));
        int sm2 = wy * 8 + jy, sn2 = wx * 8 + jx;
        int cm = ((sm2 < 56) ? 0 : ((sm2 < 60) ? 1 : 2)) * 3 +
                 ((sn2 < 56) ? 0 : ((sn2 < 60) ? 1 : 2));
        g_tabs[wloc * 4096 + e] = (uint16_t)(idx | ((cn != cm) ? 256 : 0));
    }
}

// ---------------- split-bf16 mma GEMM, cp.async + ldmatrix -------------------
// MODE 0: fp32 out + bias (+scatter). MODE 1: bf16 hi/lo out, per-head L2
// normalize (Q,K). MODE 2: bf16 hi/lo out, no normalize (V).
#define LDBROW 80                 // bytes per smem row (32 bf16 + 16B pad)
#define MATB   (128 * LDBROW)     // 10240
#define STAGEB (4 * MATB)         // 40960: Ah | Al | Bh | Bl
#define GSMEM  (2 * STAGEB)       // 81920

template <bool GATHER, bool SCATTER, int MODE>
__global__ void __launch_bounds__(256, 2) gemm_mma2(
    const __nv_bfloat16* __restrict__ Ah_, const __nv_bfloat16* __restrict__ Al_,
    const __nv_bfloat16* __restrict__ Bh_, const __nv_bfloat16* __restrict__ Bl_,
    const float* __restrict__ bias, float* __restrict__ C,
    __nv_bfloat16* __restrict__ Ch, __nv_bfloat16* __restrict__ Cl) {
    extern __shared__ char sm[];
    const uint32_t sb = smem_u32(sm);
    const int t = threadIdx.x;
    const int n0 = blockIdx.x * 128, m0 = blockIdx.y * 128;

    const int rA = t >> 1;
    const int cp0 = (t & 1) * 2;
    int garow = m0 + rA;
    if (GATHER) garow = rowmap(garow);
    const __nv_bfloat16* pAh = Ah_ + (size_t)garow * 256 + cp0 * 8;
    const __nv_bfloat16* pAl = Al_ + (size_t)garow * 256 + cp0 * 8;
    const __nv_bfloat16* pBh = Bh_ + (size_t)(n0 + rA) * 256 + cp0 * 8;
    const __nv_bfloat16* pBl = Bl_ + (size_t)(n0 + rA) * 256 + cp0 * 8;
    const uint32_t sA = (uint32_t)rA * LDBROW + cp0 * 16;

    const int lane = t & 31, w = t >> 5;
    const int wm = w >> 2, wn = w & 3;
    uint32_t aoff[4], boff[2];
    {
        int ra = wm * 64 + (lane & 7) + ((lane >> 3) & 1) * 8;
        int ac = (lane >> 4) * 16;
#pragma unroll
        for (int i = 0; i < 4; i++) aoff[i] = (uint32_t)(ra + i * 16) * LDBROW + ac;
        int rb = wn * 32 + (lane & 7) + ((lane >> 4) & 1) * 8;
        int bc = ((lane >> 3) & 1) * 16;
#pragma unroll
        for (int p = 0; p < 2; p++) boff[p] = 2 * MATB + (uint32_t)(rb + p * 16) * LDBROW + bc;
    }

    float acc[4][4][4];
#pragma unroll
    for (int i = 0; i < 4; i++)
#pragma unroll
        for (int j = 0; j < 4; j++)
#pragma unroll
            for (int p = 0; p < 4; p++) acc[i][j][p] = 0.f;

    auto stage_load = [&](int st, int chunk) {
        uint32_t base = sb + st * STAGEB + sA;
        const int go = chunk * 32;
        CP16(base,                (const char*)(pAh + go));
        CP16(base + 16,           (const char*)(pAh + go + 8));
        CP16(base + MATB,         (const char*)(pAl + go));
        CP16(base + MATB + 16,    (const char*)(pAl + go + 8));
        CP16(base + 2 * MATB,     (const char*)(pBh + go));
        CP16(base + 2 * MATB + 16,(const char*)(pBh + go + 8));
        CP16(base + 3 * MATB,     (const char*)(pBl + go));
        CP16(base + 3 * MATB + 16,(const char*)(pBl + go + 8));
        CPCOMMIT();
    };

    stage_load(0, 0);
    stage_load(1, 1);

    for (int c = 0; c < 8; c++) {
        const int st = c & 1;
        if (c < 7) { CPWAIT(1); } else { CPWAIT(0); }
        __syncthreads();
        const uint32_t stb = sb + st * STAGEB;
#pragma unroll
        for (int half = 0; half < 2; half++) {
            const uint32_t ho = half * 32;
            uint32_t bh[8], bl[8];
            ldm4(bh,     stb + boff[0] + ho);
            ldm4(bh + 4, stb + boff[1] + ho);
            ldm4(bl,     stb + boff[0] + MATB + ho);
            ldm4(bl + 4, stb + boff[1] + MATB + ho);
#pragma unroll
            for (int ip = 0; ip < 2; ip++) {
                uint32_t ah0[4], ah1[4], al0[4], al1[4];
                ldm4(ah0, stb + aoff[2 * ip] + ho);
                ldm4(ah1, stb + aoff[2 * ip + 1] + ho);
                ldm4(al0, stb + aoff[2 * ip] + MATB + ho);
                ldm4(al1, stb + aoff[2 * ip + 1] + MATB + ho);
#pragma unroll
                for (int j = 0; j < 4; j++) {
                    mma_bf16(acc[2 * ip][j],     ah0, bh + 2 * j);
                    mma_bf16(acc[2 * ip][j],     ah0, bl + 2 * j);
                    mma_bf16(acc[2 * ip][j],     al0, bh + 2 * j);
                    mma_bf16(acc[2 * ip + 1][j], ah1, bh + 2 * j);
                    mma_bf16(acc[2 * ip + 1][j], ah1, bl + 2 * j);
                    mma_bf16(acc[2 * ip + 1][j], al1, bh + 2 * j);
                }
            }
        }
        __syncthreads();
        if (c + 2 < 8) stage_load(st, c + 2);
    }

    const int g = lane >> 2, tg = lane & 3;
    if (MODE == 0) {
#pragma unroll
        for (int i = 0; i < 4; i++) {
            int row0 = m0 + wm * 64 + i * 16 + g;
            int row1 = row0 + 8;
            int gm0 = SCATTER ? rowmap(row0) : row0;
            int gm1 = SCATTER ? rowmap(row1) : row1;
            float* p0 = C + (size_t)gm0 * 256;
            float* p1 = C + (size_t)gm1 * 256;
#pragma unroll
            for (int j = 0; j < 4; j++) {
                int col = n0 + wn * 32 + j * 8 + 2 * tg;
                float2 bb = *(const float2*)&bias[col];
                *(float2*)&p0[col] = make_float2(acc[i][j][0] + bb.x, acc[i][j][1] + bb.y);
                *(float2*)&p1[col] = make_float2(acc[i][j][2] + bb.x, acc[i][j][3] + bb.y);
            }
        }
    } else {
        uint32_t* oh = (uint32_t*)Ch;
        uint32_t* ol = (uint32_t*)Cl;
        float bcol[8];
#pragma unroll
        for (int j = 0; j < 4; j++) {
            float2 bb = *(const float2*)&bias[n0 + wn * 32 + j * 8 + 2 * tg];
            bcol[2 * j] = bb.x; bcol[2 * j + 1] = bb.y;
        }
#pragma unroll
        for (int i = 0; i < 4; i++) {
#pragma unroll
            for (int ri = 0; ri < 2; ri++) {
                int row = m0 + wm * 64 + i * 16 + g + ri * 8;
                float v[8];
#pragma unroll
                for (int j = 0; j < 4; j++) {
                    v[2 * j]     = acc[i][j][2 * ri]     + bcol[2 * j];
                    v[2 * j + 1] = acc[i][j][2 * ri + 1] + bcol[2 * j + 1];
                }
                float inv = 1.f;
                if (MODE == 1) {  // per-head (32-col warp tile) L2 normalize
                    float ss = 0.f;
#pragma unroll
                    for (int u = 0; u < 8; u++) ss += v[u] * v[u];
                    ss += __shfl_xor_sync(0xffffffffu, ss, 1);
                    ss += __shfl_xor_sync(0xffffffffu, ss, 2);
                    inv = 1.f / fmaxf(sqrtf(ss), 1e-12f);
                }
                size_t b32 = (size_t)row * 128 + (n0 + wn * 32) / 2 + tg;
#pragma unroll
                for (int j = 0; j < 4; j++) {
                    float ra, rb;
                    uint32_t hh = cvt_hi2(v[2 * j] * inv, v[2 * j + 1] * inv, ra, rb);
                    oh[b32 + j * 4] = hh;
                    ol[b32 + j * 4] = cvt2(ra, rb);
                }
            }
        }
    }
}

// ---------------- tensor-core attention --------------------------------------
// Block = (window, head-pair). 8 warps = 2 heads x 4 M-quarters (16 rows each).
// All inputs pre-split bf16 hi/lo -> pure cp.async staging, zero conversion.
// V consumed via ldmatrix.trans from row-major. P stays in registers.
#define AQS  80                   // smem row bytes (32 bf16 + pad)
#define AHEAD 5120                // 64 * AQS per head
#define OF_QH 0
#define OF_QL 10240
#define OF_KH 20480
#define OF_KL 30720
#define OF_VH 40960
#define OF_VL 51200
#define OF_TAB 61440              // u16[4096]
#define OF_BF  69632              // float[2][225]
#define ATTN_SMEM 71680

__global__ void __launch_bounds__(256, 2) attn_mma(const float* __restrict__ ls) {
    extern __shared__ char sm[];
    const uint32_t sb = smem_u32(sm);
    const int t = threadIdx.x;
    const int win = blockIdx.y;
    const int hp = blockIdx.x;            // heads hp*2, hp*2+1
    const int wloc = win & 63;

    float* biasF = (float*)(sm + OF_BF);
    if (t < 225) {
        biasF[t]       = g_bias[t * 8 + hp * 2];
        biasF[225 + t] = g_bias[t * 8 + hp * 2 + 1];
    }

    // stage mask/bias table (8KB) + Q/K/V hi/lo tiles via cp.async
    {
        const char* tsrc = (const char*)g_tabs + wloc * 8192;
        CP16(sb + OF_TAB + t * 16, tsrc + t * 16);
        CP16(sb + OF_TAB + (t + 256) * 16, tsrc + (t + 256) * 16);
    }
    {
        const size_t gb = (size_t)win * 64 * 256 + hp * 64;
        const int ch = t & 3, tok = (t >> 2) & 63;
        const size_t gro = gb + (size_t)tok * 256 + ch * 8;
        const uint32_t rowpart = (uint32_t)tok * AQS + ch * 16;
        const __nv_bfloat16* srcs[6] = {g_qh, g_ql, g_kh, g_kl, g_vh, g_vl};
#pragma unroll
        for (int it = 0; it < 12; it++) {
            const int bi = it >> 1, hh2 = it & 1;   // compile-time after unroll
            CP16(sb + bi * 10240 + hh2 * AHEAD + rowpart, srcs[bi] + gro + hh2 * 32);
        }
    }
    CPCOMMIT();
    CPWAIT(0);
    __syncthreads();

    // ---- per-warp mma compute ----
    const int lane = t & 31, w = t >> 5;
    const int hh = w >> 2, wm = w & 3;
    const int head = hp * 2 + hh;
    const float scale = __expf(fminf(ls[head], 4.6051702f));
    const int g = lane >> 2, tg = lane & 3;
    const uint16_t* tab = (const uint16_t*)(sm + OF_TAB);

    const uint32_t qb = sb + OF_QH + hh * AHEAD;
    const uint32_t kb = sb + OF_KH + hh * AHEAD;

    uint32_t qh[2][4], ql[2][4];
    {
        int row = wm * 16 + (lane & 7) + ((lane >> 3) & 1) * 8;
        uint32_t col = (lane >> 4) * 16;
        uint32_t a0 = qb + (uint32_t)row * AQS + col;
        ldm4(qh[0], a0); ldm4(qh[1], a0 + 32);
        ldm4(ql[0], a0 + 10240); ldm4(ql[1], a0 + 10240 + 32);
    }
    float acc[8][4];
#pragma unroll
    for (int i = 0; i < 8; i++)
#pragma unroll
        for (int p = 0; p < 4; p++) acc[i][p] = 0.f;

    {
        int rowb = (lane & 7) + ((lane >> 4) & 1) * 8;
        uint32_t colb = ((lane >> 3) & 1) * 16;
#pragma unroll
        for (int np = 0; np < 4; np++) {
            uint32_t b0 = kb + (uint32_t)(np * 16 + rowb) * AQS + colb;
#pragma unroll
            for (int kt = 0; kt < 2; kt++) {
                uint32_t bh[4], bl[4];
                ldm4(bh, b0 + kt * 32);
                ldm4(bl, b0 + kt * 32 + 10240);
                mma_bf16(acc[2 * np],     qh[kt], bh);
                mma_bf16(acc[2 * np],     qh[kt], bl);
                mma_bf16(acc[2 * np],     ql[kt], bh);
                mma_bf16(acc[2 * np + 1], qh[kt], bh + 2);
                mma_bf16(acc[2 * np + 1], qh[kt], bl + 2);
                mma_bf16(acc[2 * np + 1], ql[kt], bh + 2);
            }
        }
    }

    // ---- scale + bias/mask + softmax in fragments ----
    const int n0r = wm * 16 + g;
    const int n1r = n0r + 8;
    const float* bf = biasF + hh * 225;
#pragma unroll
    for (int nt = 0; nt < 8; nt++) {
#pragma unroll
        for (int c = 0; c < 2; c++) {
            int m = nt * 8 + 2 * tg + c;
            uint16_t e0 = tab[n0r * 64 + m];
            acc[nt][c] = acc[nt][c] * scale + bf[e0 & 255] - 100.f * (float)(e0 >> 8);
            uint16_t e1 = tab[n1r * 64 + m];
            acc[nt][2 + c] = acc[nt][2 + c] * scale + bf[e1 & 255] - 100.f * (float)(e1 >> 8);
        }
    }
    float mx0 = -1e30f, mx1 = -1e30f;
#pragma unroll
    for (int nt = 0; nt < 8; nt++) {
        mx0 = fmaxf(mx0, fmaxf(acc[nt][0], acc[nt][1]));
        mx1 = fmaxf(mx1, fmaxf(acc[nt][2], acc[nt][3]));
    }
    mx0 = fmaxf(mx0, __shfl_xor_sync(0xffffffffu, mx0, 1));
    mx0 = fmaxf(mx0, __shfl_xor_sync(0xffffffffu, mx0, 2));
    mx1 = fmaxf(mx1, __shfl_xor_sync(0xffffffffu, mx1, 1));
    mx1 = fmaxf(mx1, __shfl_xor_sync(0xffffffffu, mx1, 2));
    float s0 = 0.f, s1 = 0.f;
#pragma unroll
    for (int nt = 0; nt < 8; nt++) {
        acc[nt][0] = __expf(acc[nt][0] - mx0); s0 += acc[nt][0];
        acc[nt][1] = __expf(acc[nt][1] - mx0); s0 += acc[nt][1];
        acc[nt][2] = __expf(acc[nt][2] - mx1); s1 += acc[nt][2];
        acc[nt][3] = __expf(acc[nt][3] - mx1); s1 += acc[nt][3];
    }
    s0 += __shfl_xor_sync(0xffffffffu, s0, 1);
    s0 += __shfl_xor_sync(0xffffffffu, s0, 2);
    s1 += __shfl_xor_sync(0xffffffffu, s1, 1);
    s1 += __shfl_xor_sync(0xffffffffu, s1, 2);
    float i0 = 1.f / s0, i1 = 1.f / s1;
#pragma unroll
    for (int nt = 0; nt < 8; nt++) {
        acc[nt][0] *= i0; acc[nt][1] *= i0; acc[nt][2] *= i1; acc[nt][3] *= i1;
    }

    // ---- PV: A from P fragments (register repack), B = V via ldmatrix.trans --
    float acco[4][4];
#pragma unroll
    for (int p = 0; p < 4; p++)
#pragma unroll
        for (int c = 0; c < 4; c++) acco[p][c] = 0.f;

    const uint32_t vb = sb + OF_VH + hh * AHEAD;
    const int kr = lane & 15;
    const uint32_t nb2 = ((lane >> 4) & 1) * 16;
#pragma unroll
    for (int j = 0; j < 4; j++) {
        uint32_t ah[4], al[4];
        float ra, rb;
        ah[0] = cvt_hi2(acc[2 * j][0],     acc[2 * j][1],     ra, rb); al[0] = cvt2(ra, rb);
        ah[1] = cvt_hi2(acc[2 * j][2],     acc[2 * j][3],     ra, rb); al[1] = cvt2(ra, rb);
        ah[2] = cvt_hi2(acc[2 * j + 1][0], acc[2 * j + 1][1], ra, rb); al[2] = cvt2(ra, rb);
        ah[3] = cvt_hi2(acc[2 * j + 1][2], acc[2 * j + 1][3], ra, rb); al[3] = cvt2(ra, rb);

        uint32_t va = vb + (uint32_t)(j * 16 + kr) * AQS + nb2;
        uint32_t vh0[4], vh1[4], vl0[4], vl1[4];
        ldm4t(vh0, va);
        ldm4t(vh1, va + 32);
        ldm4t(vl0, va + 10240);
        ldm4t(vl1, va + 10240 + 32);

        mma_bf16(acco[0], ah, vh0);     mma_bf16(acco[0], al, vh0);     mma_bf16(acco[0], ah, vl0);
        mma_bf16(acco[1], ah, vh0 + 2); mma_bf16(acco[1], al, vh0 + 2); mma_bf16(acco[1], ah, vl0 + 2);
        mma_bf16(acco[2], ah, vh1);     mma_bf16(acco[2], al, vh1);     mma_bf16(acco[2], ah, vl1);
        mma_bf16(acco[3], ah, vh1 + 2); mma_bf16(acco[3], al, vh1 + 2); mma_bf16(acco[3], ah, vl1 + 2);
    }

    // ---- store O as bf16 hi/lo (feeds the final GEMM directly) ----
    const size_t obase = (size_t)win * 64 * 256 + head * 32;
    const int tok0 = wm * 16 + g, tok1 = tok0 + 8;
#pragma unroll
    for (int p = 0; p < 4; p++) {
        int d = p * 8 + 2 * tg;
        float ra, rb;
        uint32_t h01 = cvt_hi2(acco[p][0], acco[p][1], ra, rb);
        uint32_t l01 = cvt2(ra, rb);
        *(uint32_t*)&g_oh[obase + (size_t)tok0 * 256 + d] = h01;
        *(uint32_t*)&g_ol[obase + (size_t)tok0 * 256 + d] = l01;
        uint32_t h23 = cvt_hi2(acco[p][2], acco[p][3], ra, rb);
        uint32_t l23 = cvt2(ra, rb);
        *(uint32_t*)&g_oh[obase + (size_t)tok1 * 256 + d] = h23;
        *(uint32_t*)&g_ol[obase + (size_t)tok1 * 256 + d] = l23;
    }
}

// ---------------- launch ----------------------------------------------------
extern "C" void kernel_launch(void* const* d_in, const int* in_sizes, int n_in,
                              void* d_out, int out_size) {
    const float* x  = (const float*)d_in[0];
    const float* Wq = (const float*)d_in[1];
    const float* bq = (const float*)d_in[2];
    const float* Wk = (const float*)d_in[3];
    const float* bk = (const float*)d_in[4];
    const float* Wv = (const float*)d_in[5];
    const float* bv = (const float*)d_in[6];
    const float* Wo = (const float*)d_in[7];
    const float* bo = (const float*)d_in[8];
    const float* ls = (const float*)d_in[9];
    const float* w1 = (const float*)d_in[10];
    const float* b1 = (const float*)d_in[11];
    const float* w2 = (const float*)d_in[12];
    float* out = (float*)d_out;

    __nv_bfloat16 *pxh, *pxl, *pqh, *pql, *pkh, *pkl, *pvh, *pvl, *poh, *pol, *pwh, *pwl;
    cudaGetSymbolAddress((void**)&pxh, g_xh);
    cudaGetSymbolAddress((void**)&pxl, g_xl);
    cudaGetSymbolAddress((void**)&pqh, g_qh);
    cudaGetSymbolAddress((void**)&pql, g_ql);
    cudaGetSymbolAddress((void**)&pkh, g_kh);
    cudaGetSymbolAddress((void**)&pkl, g_kl);
    cudaGetSymbolAddress((void**)&pvh, g_vh);
    cudaGetSymbolAddress((void**)&pvl, g_vl);
    cudaGetSymbolAddress((void**)&poh, g_oh);
    cudaGetSymbolAddress((void**)&pol, g_ol);
    cudaGetSymbolAddress((void**)&pwh, g_wh);
    cudaGetSymbolAddress((void**)&pwl, g_wl);

    cudaFuncSetAttribute(gemm_mma2<true, false, 1>,
                         cudaFuncAttributeMaxDynamicSharedMemorySize, GSMEM);
    cudaFuncSetAttribute(gemm_mma2<true, false, 2>,
                         cudaFuncAttributeMaxDynamicSharedMemorySize, GSMEM);
    cudaFuncSetAttribute(gemm_mma2<false, true, 0>,
                         cudaFuncAttributeMaxDynamicSharedMemorySize, GSMEM);
    cudaFuncSetAttribute(attn_mma,
                         cudaFuncAttributeMaxDynamicSharedMemorySize, ATTN_SMEM);

    cpb_kernel<<<8, 256>>>(w1, b1, w2);
    tab_kernel<<<64, 256>>>();

    const int xn4 = TOK * CD / 4;
    const int wn4 = CD * CD / 4;
    split_kernel<<<xn4 / 256, 256>>>(x, pxh, pxl, xn4);
    split_kernel<<<wn4 / 256, 256>>>(Wq, pwh + 0 * CD * CD, pwl + 0 * CD * CD, wn4);
    split_kernel<<<wn4 / 256, 256>>>(Wk, pwh + 1 * CD * CD, pwl + 1 * CD * CD, wn4);
    split_kernel<<<wn4 / 256, 256>>>(Wv, pwh + 2 * CD * CD, pwl + 2 * CD * CD, wn4);
    split_kernel<<<wn4 / 256, 256>>>(Wo, pwh + 3 * CD * CD, pwl + 3 * CD * CD, wn4);

    dim3 gg(2, 1024);
    gemm_mma2<true, false, 1><<<gg, 256, GSMEM>>>(
        pxh, pxl, pwh + 0 * CD * CD, pwl + 0 * CD * CD, bq, nullptr, pqh, pql);
    gemm_mma2<true, false, 1><<<gg, 256, GSMEM>>>(
        pxh, pxl, pwh + 1 * CD * CD, pwl + 1 * CD * CD, bk, nullptr, pkh, pkl);
    gemm_mma2<true, false, 2><<<gg, 256, GSMEM>>>(
        pxh, pxl, pwh + 2 * CD * CD, pwl + 2 * CD * CD, bv, nullptr, pvh, pvl);

    attn_mma<<<dim3(4, 2048), 256, ATTN_SMEM>>>(ls);

    gemm_mma2<false, true, 0><<<gg, 256, GSMEM>>>(
        poh, pol, pwh + 3 * CD * CD, pwl + 3 * CD * CD, bo, out, nullptr, nullptr);
}

// round 8
// speedup vs baseline: 1.9123x; 1.0334x over previous
#include <cuda_runtime.h>
#include <cuda_bf16.h>
#include <cstdint>

#define TOK 131072   // B*H*W = 32*64*64 tokens
#define CD  256
#define TOKCD (TOK * CD)

// ---------------- scratch (device globals; no allocations allowed) ----------
__device__ float g_bias[225 * 8];
__device__ __nv_bfloat16 g_xh[TOKCD], g_xl[TOKCD];
__device__ __nv_bfloat16 g_qkvh[3 * TOKCD], g_qkvl[3 * TOKCD];
__device__ __nv_bfloat16 g_oh[TOKCD], g_ol[TOKCD];
__device__ __nv_bfloat16 g_wh[4 * CD * CD], g_wl[4 * CD * CD];
__device__ __align__(16) uint16_t g_tabs[64 * 4096];

// ---------------- helpers ----------------------------------------------------
__device__ __forceinline__ uint32_t smem_u32(const void* p) {
    uint32_t a;
    asm("{ .reg .u64 t; cvta.to.shared.u64 t, %1; cvt.u32.u64 %0, t; }"
        : "=r"(a) : "l"(p));
    return a;
}

// token index (window order) -> row in the [B,H,W] image (shift+partition map)
__device__ __forceinline__ int rowmap(int m) {
    int win = m >> 6, n = m & 63;
    int b = win >> 6, w = win & 63;
    int wy = w >> 3, wx = w & 7;
    int iy = n >> 3, ix = n & 7;
    int gi = (wy * 8 + iy + 4) & 63;
    int gj = (wx * 8 + ix + 4) & 63;
    return (b * 64 + gi) * 64 + gj;
}

// bf16 split helpers
__device__ __forceinline__ uint32_t cvt_hi2(float a, float b, float& ra, float& rb) {
    __nv_bfloat16 ha = __float2bfloat16_rn(a), hb = __float2bfloat16_rn(b);
    ra = a - __bfloat162float(ha);
    rb = b - __bfloat162float(hb);
    __nv_bfloat162 p = __halves2bfloat162(ha, hb);
    return *(uint32_t*)&p;
}
__device__ __forceinline__ uint32_t cvt2(float a, float b) {
    __nv_bfloat162 p = __halves2bfloat162(__float2bfloat16_rn(a), __float2bfloat16_rn(b));
    return *(uint32_t*)&p;
}

__device__ __forceinline__ void mma_bf16(float* d, const uint32_t* a, const uint32_t* b) {
    asm volatile(
        "mma.sync.aligned.m16n8k16.row.col.f32.bf16.bf16.f32 "
        "{%0,%1,%2,%3}, {%4,%5,%6,%7}, {%8,%9}, {%0,%1,%2,%3};"
        : "+f"(d[0]), "+f"(d[1]), "+f"(d[2]), "+f"(d[3])
        : "r"(a[0]), "r"(a[1]), "r"(a[2]), "r"(a[3]), "r"(b[0]), "r"(b[1]));
}
__device__ __forceinline__ void ldm4(uint32_t* r, uint32_t addr) {
    asm volatile("ldmatrix.sync.aligned.m8n8.x4.shared.b16 {%0,%1,%2,%3}, [%4];"
                 : "=r"(r[0]), "=r"(r[1]), "=r"(r[2]), "=r"(r[3]) : "r"(addr));
}
__device__ __forceinline__ void ldm4t(uint32_t* r, uint32_t addr) {
    asm volatile("ldmatrix.sync.aligned.m8n8.x4.trans.shared.b16 {%0,%1,%2,%3}, [%4];"
                 : "=r"(r[0]), "=r"(r[1]), "=r"(r[2]), "=r"(r[3]) : "r"(addr));
}
#define CP16(s, g) asm volatile("cp.async.cg.shared.global [%0], [%1], 16;" :: "r"(s), "l"(g))
#define CPCOMMIT() asm volatile("cp.async.commit_group;" ::: "memory")
#define CPWAIT(n)  asm volatile("cp.async.wait_group %0;" :: "n"(n) : "memory")

// ---------------- fp32 -> bf16 hi/lo split pass ------------------------------
__global__ void split_kernel(const float* __restrict__ src, __nv_bfloat16* __restrict__ hi,
                             __nv_bfloat16* __restrict__ lo, int n4) {
    int i = blockIdx.x * blockDim.x + threadIdx.x;
    if (i >= n4) return;
    float4 v = ((const float4*)src)[i];
    float r0, r1, r2, r3;
    uint32_t h01 = cvt_hi2(v.x, v.y, r0, r1);
    uint32_t h23 = cvt_hi2(v.z, v.w, r2, r3);
    ((uint32_t*)hi)[2 * i] = h01;
    ((uint32_t*)hi)[2 * i + 1] = h23;
    ((uint32_t*)lo)[2 * i] = cvt2(r0, r1);
    ((uint32_t*)lo)[2 * i + 1] = cvt2(r2, r3);
}

// ---------------- CPB-MLP (parallel over heads) ------------------------------
__device__ __forceinline__ float cpb_coord(int a) {
    float r = (float)(a - 7);
    float v = r * (8.0f / 7.0f);
    float s = (v > 0.f) ? 1.f : ((v < 0.f) ? -1.f : 0.f);
    return s * log2f(fabsf(v) + 1.f) * (1.0f / 3.0f);
}

__global__ void cpb_kernel(const float* __restrict__ w1, const float* __restrict__ b1,
                           const float* __restrict__ w2) {
    int t = threadIdx.x;
    int h = blockIdx.x;
    if (t >= 225) return;
    float ta = cpb_coord(t / 15);
    float tb = cpb_coord(t % 15);
    float acc = 0.f;
    for (int j = 0; j < 512; j++) {
        float hd = ta * w1[2 * j] + tb * w1[2 * j + 1] + b1[j];
        hd = fmaxf(hd, 0.f);
        acc += hd * w2[h * 512 + j];
    }
    g_bias[t * 8 + h] = 16.f / (1.f + expf(-acc));
}

// ---------------- per-window-position bias-index + mask tables ---------------
__global__ void tab_kernel() {
    int wloc = blockIdx.x;
    int wy = wloc >> 3, wx = wloc & 7;
    for (int e = threadIdx.x; e < 4096; e += 256) {
        int n = e >> 6, m = e & 63;
        int iy = n >> 3, ix = n & 7, jy = m >> 3, jx = m & 7;
        int idx = (iy - jy + 7) * 15 + (ix - jx + 7);
        int si = wy * 8 + iy, sj = wx * 8 + ix;
        int cn = ((si < 56) ? 0 : ((si < 60) ? 1 : 2)) * 3 +
                 ((sj < 56) ? 0 : ((sj < 60) ? 1 : 2));
        int sm2 = wy * 8 + jy, sn2 = wx * 8 + jx;
        int cm = ((sm2 < 56) ? 0 : ((sm2 < 60) ? 1 : 2)) * 3 +
                 ((sn2 < 56) ? 0 : ((sn2 < 60) ? 1 : 2));
        g_tabs[wloc * 4096 + e] = (uint16_t)(idx | ((cn != cm) ? 256 : 0));
    }
}

// ---------------- split-bf16 mma GEMM, cp.async + ldmatrix -------------------
// MODE 0: O-gemm  — grid(2,1024), fp32 out + bias + scatter.
// MODE 1: QKV-gemm — grid(6,1024), widx=bx>>1 selects W/bias/output,
//         gather A rows, bf16 hi/lo out, L2-normalize per head for Q,K.
#define LDBROW 80                 // bytes per smem row (32 bf16 + 16B pad)
#define MATB   (128 * LDBROW)     // 10240
#define STAGEB (4 * MATB)         // 40960: Ah | Al | Bh | Bl
#define GSMEM  (2 * STAGEB)       // 81920

template <int MODE>
__global__ void __launch_bounds__(256, 2) gemm_mma2(
    const __nv_bfloat16* __restrict__ Ah_, const __nv_bfloat16* __restrict__ Al_,
    const __nv_bfloat16* __restrict__ Wh_, const __nv_bfloat16* __restrict__ Wl_,
    const float* __restrict__ b0_, const float* __restrict__ b1_,
    const float* __restrict__ b2_, float* __restrict__ C,
    __nv_bfloat16* __restrict__ ChB, __nv_bfloat16* __restrict__ ClB) {
    extern __shared__ char sm[];
    const uint32_t sb = smem_u32(sm);
    const int t = threadIdx.x;
    const int m0 = blockIdx.y * 128;

    int n0, widx;
    const float* bias;
    if (MODE == 1) {
        widx = blockIdx.x >> 1;
        n0 = (blockIdx.x & 1) * 128;
        bias = (widx == 0) ? b0_ : ((widx == 1) ? b1_ : b2_);
    } else {
        widx = 0;
        n0 = blockIdx.x * 128;
        bias = b0_;
    }
    const __nv_bfloat16* Bh_ = Wh_ + (size_t)widx * CD * CD;
    const __nv_bfloat16* Bl_ = Wl_ + (size_t)widx * CD * CD;

    const int rA = t >> 1;
    const int cp0 = (t & 1) * 2;
    int garow = m0 + rA;
    if (MODE == 1) garow = rowmap(garow);
    const __nv_bfloat16* pAh = Ah_ + (size_t)garow * 256 + cp0 * 8;
    const __nv_bfloat16* pAl = Al_ + (size_t)garow * 256 + cp0 * 8;
    const __nv_bfloat16* pBh = Bh_ + (size_t)(n0 + rA) * 256 + cp0 * 8;
    const __nv_bfloat16* pBl = Bl_ + (size_t)(n0 + rA) * 256 + cp0 * 8;
    const uint32_t sA = (uint32_t)rA * LDBROW + cp0 * 16;

    const int lane = t & 31, w = t >> 5;
    const int wm = w >> 2, wn = w & 3;
    uint32_t aoff[4], boff[2];
    {
        int ra = wm * 64 + (lane & 7) + ((lane >> 3) & 1) * 8;
        int ac = (lane >> 4) * 16;
#pragma unroll
        for (int i = 0; i < 4; i++) aoff[i] = (uint32_t)(ra + i * 16) * LDBROW + ac;
        int rb = wn * 32 + (lane & 7) + ((lane >> 4) & 1) * 8;
        int bc = ((lane >> 3) & 1) * 16;
#pragma unroll
        for (int p = 0; p < 2; p++) boff[p] = 2 * MATB + (uint32_t)(rb + p * 16) * LDBROW + bc;
    }

    float acc[4][4][4];
#pragma unroll
    for (int i = 0; i < 4; i++)
#pragma unroll
        for (int j = 0; j < 4; j++)
#pragma unroll
            for (int p = 0; p < 4; p++) acc[i][j][p] = 0.f;

    auto stage_load = [&](int st, int chunk) {
        uint32_t base = sb + st * STAGEB + sA;
        const int go = chunk * 32;
        CP16(base,                (const char*)(pAh + go));
        CP16(base + 16,           (const char*)(pAh + go + 8));
        CP16(base + MATB,         (const char*)(pAl + go));
        CP16(base + MATB + 16,    (const char*)(pAl + go + 8));
        CP16(base + 2 * MATB,     (const char*)(pBh + go));
        CP16(base + 2 * MATB + 16,(const char*)(pBh + go + 8));
        CP16(base + 3 * MATB,     (const char*)(pBl + go));
        CP16(base + 3 * MATB + 16,(const char*)(pBl + go + 8));
        CPCOMMIT();
    };

    stage_load(0, 0);
    stage_load(1, 1);

    for (int c = 0; c < 8; c++) {
        const int st = c & 1;
        if (c < 7) { CPWAIT(1); } else { CPWAIT(0); }
        __syncthreads();
        const uint32_t stb = sb + st * STAGEB;
#pragma unroll
        for (int half = 0; half < 2; half++) {
            const uint32_t ho = half * 32;
            uint32_t bh[8], bl[8];
            ldm4(bh,     stb + boff[0] + ho);
            ldm4(bh + 4, stb + boff[1] + ho);
            ldm4(bl,     stb + boff[0] + MATB + ho);
            ldm4(bl + 4, stb + boff[1] + MATB + ho);
#pragma unroll
            for (int ip = 0; ip < 2; ip++) {
                uint32_t ah0[4], ah1[4], al0[4], al1[4];
                ldm4(ah0, stb + aoff[2 * ip] + ho);
                ldm4(ah1, stb + aoff[2 * ip + 1] + ho);
                ldm4(al0, stb + aoff[2 * ip] + MATB + ho);
                ldm4(al1, stb + aoff[2 * ip + 1] + MATB + ho);
                // term-major ordering: same-accumulator reuse distance = 8
#pragma unroll
                for (int j = 0; j < 4; j++) {
                    mma_bf16(acc[2 * ip][j],     ah0, bh + 2 * j);
                    mma_bf16(acc[2 * ip + 1][j], ah1, bh + 2 * j);
                }
#pragma unroll
                for (int j = 0; j < 4; j++) {
                    mma_bf16(acc[2 * ip][j],     ah0, bl + 2 * j);
                    mma_bf16(acc[2 * ip + 1][j], ah1, bl + 2 * j);
                }
#pragma unroll
                for (int j = 0; j < 4; j++) {
                    mma_bf16(acc[2 * ip][j],     al0, bh + 2 * j);
                    mma_bf16(acc[2 * ip + 1][j], al1, bh + 2 * j);
                }
            }
        }
        __syncthreads();
        if (c + 2 < 8) stage_load(st, c + 2);
    }

    const int g = lane >> 2, tg = lane & 3;
    if (MODE == 0) {
#pragma unroll
        for (int i = 0; i < 4; i++) {
            int row0 = m0 + wm * 64 + i * 16 + g;
            int row1 = row0 + 8;
            int gm0 = rowmap(row0);
            int gm1 = rowmap(row1);
            float* p0 = C + (size_t)gm0 * 256;
            float* p1 = C + (size_t)gm1 * 256;
#pragma unroll
            for (int j = 0; j < 4; j++) {
                int col = n0 + wn * 32 + j * 8 + 2 * tg;
                float2 bb = *(const float2*)&bias[col];
                *(float2*)&p0[col] = make_float2(acc[i][j][0] + bb.x, acc[i][j][1] + bb.y);
                *(float2*)&p1[col] = make_float2(acc[i][j][2] + bb.x, acc[i][j][3] + bb.y);
            }
        }
    } else {
        const bool donorm = (widx < 2);
        uint32_t* oh = (uint32_t*)(ChB + (size_t)widx * TOKCD);
        uint32_t* ol = (uint32_t*)(ClB + (size_t)widx * TOKCD);
        float bcol[8];
#pragma unroll
        for (int j = 0; j < 4; j++) {
            float2 bb = *(const float2*)&bias[n0 + wn * 32 + j * 8 + 2 * tg];
            bcol[2 * j] = bb.x; bcol[2 * j + 1] = bb.y;
        }
#pragma unroll
        for (int i = 0; i < 4; i++) {
#pragma unroll
            for (int ri = 0; ri < 2; ri++) {
                int row = m0 + wm * 64 + i * 16 + g + ri * 8;
                float v[8];
#pragma unroll
                for (int j = 0; j < 4; j++) {
                    v[2 * j]     = acc[i][j][2 * ri]     + bcol[2 * j];
                    v[2 * j + 1] = acc[i][j][2 * ri + 1] + bcol[2 * j + 1];
                }
                float inv = 1.f;
                if (donorm) {  // per-head (32-col warp tile) L2 normalize
                    float ss = 0.f;
#pragma unroll
                    for (int u = 0; u < 8; u++) ss += v[u] * v[u];
                    ss += __shfl_xor_sync(0xffffffffu, ss, 1);
                    ss += __shfl_xor_sync(0xffffffffu, ss, 2);
                    inv = 1.f / fmaxf(sqrtf(ss), 1e-12f);
                }
                size_t b32 = (size_t)row * 128 + (n0 + wn * 32) / 2 + tg;
#pragma unroll
                for (int j = 0; j < 4; j++) {
                    float ra, rb;
                    uint32_t hh = cvt_hi2(v[2 * j] * inv, v[2 * j + 1] * inv, ra, rb);
                    oh[b32 + j * 4] = hh;
                    ol[b32 + j * 4] = cvt2(ra, rb);
                }
            }
        }
    }
}

// ---------------- tensor-core attention --------------------------------------
// Block = (window, head-pair). 8 warps = 2 heads x 4 M-quarters (16 rows each).
// 2-group cp.async pipeline: Q/K first (QK^T overlaps V+table load).
#define AQS  80                   // smem row bytes (32 bf16 + pad)
#define AHEAD 5120                // 64 * AQS per head
#define OF_QH 0
#define OF_QL 10240
#define OF_KH 20480
#define OF_KL 30720
#define OF_VH 40960
#define OF_VL 51200
#define OF_TAB 61440              // u16[4096]
#define OF_BF  69632              // float[2][225]
#define ATTN_SMEM 71680

__global__ void __launch_bounds__(256, 2) attn_mma(const float* __restrict__ ls) {
    extern __shared__ char sm[];
    const uint32_t sb = smem_u32(sm);
    const int t = threadIdx.x;
    const int win = blockIdx.y;
    const int hp = blockIdx.x;            // heads hp*2, hp*2+1
    const int wloc = win & 63;

    float* biasF = (float*)(sm + OF_BF);
    if (t < 225) {
        biasF[t]       = g_bias[t * 8 + hp * 2];
        biasF[225 + t] = g_bias[t * 8 + hp * 2 + 1];
    }

    const size_t gb = (size_t)win * 64 * 256 + hp * 64;
    const int ch = t & 3, tok = (t >> 2) & 63;
    const size_t gro = gb + (size_t)tok * 256 + ch * 8;
    const uint32_t rowpart = (uint32_t)tok * AQS + ch * 16;

    // group 1: Q,K hi/lo
    {
        const __nv_bfloat16* srcs[4] = {g_qkvh, g_qkvl, g_qkvh + TOKCD, g_qkvl + TOKCD};
#pragma unroll
        for (int it = 0; it < 8; it++) {
            const int bi = it >> 1, hh2 = it & 1;
            CP16(sb + bi * 10240 + hh2 * AHEAD + rowpart, srcs[bi] + gro + hh2 * 32);
        }
    }
    CPCOMMIT();
    // group 2: V hi/lo + mask/bias table
    {
#pragma unroll
        for (int it = 0; it < 4; it++) {
            const int bi = it >> 1, hh2 = it & 1;
            CP16(sb + OF_VH + bi * 10240 + hh2 * AHEAD + rowpart,
                 (bi ? g_qkvl : g_qkvh) + 2 * TOKCD + gro + hh2 * 32);
        }
        const char* tsrc = (const char*)g_tabs + wloc * 8192;
        CP16(sb + OF_TAB + t * 16, tsrc + t * 16);
        CP16(sb + OF_TAB + (t + 256) * 16, tsrc + (t + 256) * 16);
    }
    CPCOMMIT();

    CPWAIT(1);
    __syncthreads();

    // ---- per-warp mma compute ----
    const int lane = t & 31, w = t >> 5;
    const int hh = w >> 2, wm = w & 3;
    const int head = hp * 2 + hh;
    const float scale = __expf(fminf(ls[head], 4.6051702f));
    const int g = lane >> 2, tg = lane & 3;
    const uint16_t* tab = (const uint16_t*)(sm + OF_TAB);

    const uint32_t qb = sb + OF_QH + hh * AHEAD;
    const uint32_t kb = sb + OF_KH + hh * AHEAD;

    uint32_t qh[2][4], ql[2][4];
    {
        int row = wm * 16 + (lane & 7) + ((lane >> 3) & 1) * 8;
        uint32_t col = (lane >> 4) * 16;
        uint32_t a0 = qb + (uint32_t)row * AQS + col;
        ldm4(qh[0], a0); ldm4(qh[1], a0 + 32);
        ldm4(ql[0], a0 + 10240); ldm4(ql[1], a0 + 10240 + 32);
    }
    float acc[8][4];
#pragma unroll
    for (int i = 0; i < 8; i++)
#pragma unroll
        for (int p = 0; p < 4; p++) acc[i][p] = 0.f;

    {
        int rowb = (lane & 7) + ((lane >> 4) & 1) * 8;
        uint32_t colb = ((lane >> 3) & 1) * 16;
#pragma unroll
        for (int npp = 0; npp < 2; npp++) {
            uint32_t bh[2][2][4], bl[2][2][4];   // [npi][kt][4]
#pragma unroll
            for (int npi = 0; npi < 2; npi++) {
                int np = 2 * npp + npi;
                uint32_t b0 = kb + (uint32_t)(np * 16 + rowb) * AQS + colb;
#pragma unroll
                for (int kt = 0; kt < 2; kt++) {
                    ldm4(bh[npi][kt], b0 + kt * 32);
                    ldm4(bl[npi][kt], b0 + kt * 32 + 10240);
                }
            }
            float* a0 = acc[4 * npp];
            float* a1 = acc[4 * npp + 1];
            float* a2 = acc[4 * npp + 2];
            float* a3 = acc[4 * npp + 3];
            // term-major: 4 distinct accs between same-acc reuses
#pragma unroll
            for (int kt = 0; kt < 2; kt++) {
                mma_bf16(a0, qh[kt], bh[0][kt]);
                mma_bf16(a1, qh[kt], bh[0][kt] + 2);
                mma_bf16(a2, qh[kt], bh[1][kt]);
                mma_bf16(a3, qh[kt], bh[1][kt] + 2);
            }
#pragma unroll
            for (int kt = 0; kt < 2; kt++) {
                mma_bf16(a0, qh[kt], bl[0][kt]);
                mma_bf16(a1, qh[kt], bl[0][kt] + 2);
                mma_bf16(a2, qh[kt], bl[1][kt]);
                mma_bf16(a3, qh[kt], bl[1][kt] + 2);
            }
#pragma unroll
            for (int kt = 0; kt < 2; kt++) {
                mma_bf16(a0, ql[kt], bh[0][kt]);
                mma_bf16(a1, ql[kt], bh[0][kt] + 2);
                mma_bf16(a2, ql[kt], bh[1][kt]);
                mma_bf16(a3, ql[kt], bh[1][kt] + 2);
            }
        }
    }

    // V + table must be resident before bias/mask application
    CPWAIT(0);
    __syncthreads();

    // ---- scale + bias/mask + softmax in fragments ----
    const int n0r = wm * 16 + g;
    const int n1r = n0r + 8;
    const float* bf = biasF + hh * 225;
#pragma unroll
    for (int nt = 0; nt < 8; nt++) {
#pragma unroll
        for (int c = 0; c < 2; c++) {
            int m = nt * 8 + 2 * tg + c;
            uint16_t e0 = tab[n0r * 64 + m];
            acc[nt][c] = acc[nt][c] * scale + bf[e0 & 255] - 100.f * (float)(e0 >> 8);
            uint16_t e1 = tab[n1r * 64 + m];
            acc[nt][2 + c] = acc[nt][2 + c] * scale + bf[e1 & 255] - 100.f * (float)(e1 >> 8);
        }
    }
    float mx0 = -1e30f, mx1 = -1e30f;
#pragma unroll
    for (int nt = 0; nt < 8; nt++) {
        mx0 = fmaxf(mx0, fmaxf(acc[nt][0], acc[nt][1]));
        mx1 = fmaxf(mx1, fmaxf(acc[nt][2], acc[nt][3]));
    }
    mx0 = fmaxf(mx0, __shfl_xor_sync(0xffffffffu, mx0, 1));
    mx0 = fmaxf(mx0, __shfl_xor_sync(0xffffffffu, mx0, 2));
    mx1 = fmaxf(mx1, __shfl_xor_sync(0xffffffffu, mx1, 1));
    mx1 = fmaxf(mx1, __shfl_xor_sync(0xffffffffu, mx1, 2));
    float s0 = 0.f, s1 = 0.f;
#pragma unroll
    for (int nt = 0; nt < 8; nt++) {
        acc[nt][0] = __expf(acc[nt][0] - mx0); s0 += acc[nt][0];
        acc[nt][1] = __expf(acc[nt][1] - mx0); s0 += acc[nt][1];
        acc[nt][2] = __expf(acc[nt][2] - mx1); s1 += acc[nt][2];
        acc[nt][3] = __expf(acc[nt][3] - mx1); s1 += acc[nt][3];
    }
    s0 += __shfl_xor_sync(0xffffffffu, s0, 1);
    s0 += __shfl_xor_sync(0xffffffffu, s0, 2);
    s1 += __shfl_xor_sync(0xffffffffu, s1, 1);
    s1 += __shfl_xor_sync(0xffffffffu, s1, 2);
    float i0 = 1.f / s0, i1 = 1.f / s1;
#pragma unroll
    for (int nt = 0; nt < 8; nt++) {
        acc[nt][0] *= i0; acc[nt][1] *= i0; acc[nt][2] *= i1; acc[nt][3] *= i1;
    }

    // ---- PV: A from P fragments (register repack), B = V via ldmatrix.trans --
    float acco[4][4];
#pragma unroll
    for (int p = 0; p < 4; p++)
#pragma unroll
        for (int c = 0; c < 4; c++) acco[p][c] = 0.f;

    const uint32_t vb = sb + OF_VH + hh * AHEAD;
    const int kr = lane & 15;
    const uint32_t nb2 = ((lane >> 4) & 1) * 16;
#pragma unroll
    for (int j = 0; j < 4; j++) {
        uint32_t ah[4], al[4];
        float ra, rb;
        ah[0] = cvt_hi2(acc[2 * j][0],     acc[2 * j][1],     ra, rb); al[0] = cvt2(ra, rb);
        ah[1] = cvt_hi2(acc[2 * j][2],     acc[2 * j][3],     ra, rb); al[1] = cvt2(ra, rb);
        ah[2] = cvt_hi2(acc[2 * j + 1][0], acc[2 * j + 1][1], ra, rb); al[2] = cvt2(ra, rb);
        ah[3] = cvt_hi2(acc[2 * j + 1][2], acc[2 * j + 1][3], ra, rb); al[3] = cvt2(ra, rb);

        uint32_t va = vb + (uint32_t)(j * 16 + kr) * AQS + nb2;
        uint32_t vh0[4], vh1[4], vl0[4], vl1[4];
        ldm4t(vh0, va);
        ldm4t(vh1, va + 32);
        ldm4t(vl0, va + 10240);
        ldm4t(vl1, va + 10240 + 32);

        // term-major across the 4 acco targets (reuse distance 4)
        mma_bf16(acco[0], ah, vh0);
        mma_bf16(acco[1], ah, vh0 + 2);
        mma_bf16(acco[2], ah, vh1);
        mma_bf16(acco[3], ah, vh1 + 2);
        mma_bf16(acco[0], al, vh0);
        mma_bf16(acco[1], al, vh0 + 2);
        mma_bf16(acco[2], al, vh1);
        mma_bf16(acco[3], al, vh1 + 2);
        mma_bf16(acco[0], ah, vl0);
        mma_bf16(acco[1], ah, vl0 + 2);
        mma_bf16(acco[2], ah, vl1);
        mma_bf16(acco[3], ah, vl1 + 2);
    }

    // ---- store O as bf16 hi/lo (feeds the final GEMM directly) ----
    const size_t obase = (size_t)win * 64 * 256 + head * 32;
    const int tok0 = wm * 16 + g, tok1 = tok0 + 8;
#pragma unroll
    for (int p = 0; p < 4; p++) {
        int d = p * 8 + 2 * tg;
        float ra, rb;
        uint32_t h01 = cvt_hi2(acco[p][0], acco[p][1], ra, rb);
        uint32_t l01 = cvt2(ra, rb);
        *(uint32_t*)&g_oh[obase + (size_t)tok0 * 256 + d] = h01;
        *(uint32_t*)&g_ol[obase + (size_t)tok0 * 256 + d] = l01;
        uint32_t h23 = cvt_hi2(acco[p][2], acco[p][3], ra, rb);
        uint32_t l23 = cvt2(ra, rb);
        *(uint32_t*)&g_oh[obase + (size_t)tok1 * 256 + d] = h23;
        *(uint32_t*)&g_ol[obase + (size_t)tok1 * 256 + d] = l23;
    }
}

// ---------------- launch ----------------------------------------------------
extern "C" void kernel_launch(void* const* d_in, const int* in_sizes, int n_in,
                              void* d_out, int out_size) {
    const float* x  = (const float*)d_in[0];
    const float* Wq = (const float*)d_in[1];
    const float* bq = (const float*)d_in[2];
    const float* Wk = (const float*)d_in[3];
    const float* bk = (const float*)d_in[4];
    const float* Wv = (const float*)d_in[5];
    const float* bv = (const float*)d_in[6];
    const float* Wo = (const float*)d_in[7];
    const float* bo = (const float*)d_in[8];
    const float* ls = (const float*)d_in[9];
    const float* w1 = (const float*)d_in[10];
    const float* b1 = (const float*)d_in[11];
    const float* w2 = (const float*)d_in[12];
    float* out = (float*)d_out;

    __nv_bfloat16 *pxh, *pxl, *pqkvh, *pqkvl, *poh, *pol, *pwh, *pwl;
    cudaGetSymbolAddress((void**)&pxh, g_xh);
    cudaGetSymbolAddress((void**)&pxl, g_xl);
    cudaGetSymbolAddress((void**)&pqkvh, g_qkvh);
    cudaGetSymbolAddress((void**)&pqkvl, g_qkvl);
    cudaGetSymbolAddress((void**)&poh, g_oh);
    cudaGetSymbolAddress((void**)&pol, g_ol);
    cudaGetSymbolAddress((void**)&pwh, g_wh);
    cudaGetSymbolAddress((void**)&pwl, g_wl);

    cudaFuncSetAttribute(gemm_mma2<0>,
                         cudaFuncAttributeMaxDynamicSharedMemorySize, GSMEM);
    cudaFuncSetAttribute(gemm_mma2<1>,
                         cudaFuncAttributeMaxDynamicSharedMemorySize, GSMEM);
    cudaFuncSetAttribute(attn_mma,
                         cudaFuncAttributeMaxDynamicSharedMemorySize, ATTN_SMEM);

    cpb_kernel<<<8, 256>>>(w1, b1, w2);
    tab_kernel<<<64, 256>>>();

    const int xn4 = TOKCD / 4;
    const int wn4 = CD * CD / 4;
    split_kernel<<<xn4 / 256, 256>>>(x, pxh, pxl, xn4);
    split_kernel<<<wn4 / 256, 256>>>(Wq, pwh + 0 * CD * CD, pwl + 0 * CD * CD, wn4);
    split_kernel<<<wn4 / 256, 256>>>(Wk, pwh + 1 * CD * CD, pwl + 1 * CD * CD, wn4);
    split_kernel<<<wn4 / 256, 256>>>(Wv, pwh + 2 * CD * CD, pwl + 2 * CD * CD, wn4);
    split_kernel<<<wn4 / 256, 256>>>(Wo, pwh + 3 * CD * CD, pwl + 3 * CD * CD, wn4);

    // merged Q/K/V projection (one launch, widx = blockIdx.x>>1)
    gemm_mma2<1><<<dim3(6, 1024), 256, GSMEM>>>(
        pxh, pxl, pwh, pwl, bq, bk, bv, nullptr, pqkvh, pqkvl);

    attn_mma<<<dim3(4, 2048), 256, ATTN_SMEM>>>(ls);

    gemm_mma2<0><<<dim3(2, 1024), 256, GSMEM>>>(
        poh, pol, pwh + 3 * CD * CD, pwl + 3 * CD * CD, bo, nullptr, nullptr, out,
        nullptr, nullptr);
}